// round 14
// baseline (speedup 1.0000x reference)
#include <cuda_runtime.h>
#include <cuda_bf16.h>
#include <cstdint>
#include <math.h>

#define BATCH   8
#define TT      2048
#define BT      16384      // BATCH*TT
#define DMODEL  1024
#define NP      512        // padded projection columns (450 real)
#define RECW    516        // floats per (b,t) scan record (float4 aligned)
#define RECW2   388        // floats per (b,t) matrix-pass record (S,D,k1,k2,scalars)
#define K1EXP   3072       // 3 * 1024  (bf16 split blocks: [hi, lo, hi])
#define K2EXP   384        // 12 * 32   (interleaved per-lane triplets)
#define LCH     128        // chunk length
#define NCH     (BT / LCH) // 128 chunks (16 per batch)

// ---------------- device scratch (no allocations allowed) ----------------
__device__ __align__(16) __nv_bfloat16 g_B1[(size_t)NP * K1EXP];        // B for GEMM1
__device__ __align__(16) __nv_bfloat16 g_B2[(size_t)DMODEL * K2EXP];    // B for GEMM2
__device__ __align__(16) __nv_bfloat16 g_Hexp[(size_t)BT * K2EXP];      // A for GEMM2
__device__ float g_P[(size_t)BT * NP];                                  // raw projections fp32
__device__ __align__(16) float g_rec[(size_t)BT * RECW];                // scan records (lane layout)
__device__ __align__(16) float g_rec2[(size_t)BT * RECW2];              // matrix-pass records (plain)
__device__ __align__(16) float g_Phi[(size_t)NCH * 128 * 128];          // chunk transition [ch][col][row]
__device__ __align__(16) float g_pend[NCH * 128];                       // chunk particular soln (P layout)
__device__ __align__(16) float g_hend[NCH * 128];                       // chunk end states (P layout)

// ---------------- helpers ----------------
__device__ __forceinline__ void split_bf16(float v, __nv_bfloat16& hi, __nv_bfloat16& lo)
{
    hi = __float2bfloat16(v);
    lo = __float2bfloat16(v - __bfloat162float(hi));
}

__device__ __forceinline__ unsigned pack2(__nv_bfloat16 a, __nv_bfloat16 b)
{
    __nv_bfloat162 p(a, b);
    return *(unsigned*)&p;
}

__device__ __forceinline__ uint32_t smem_u32(const void* p)
{
    uint32_t a;
    asm("{ .reg .u64 t; cvta.to.shared.u64 t, %1; cvt.u32.u64 %0, t; }" : "=r"(a) : "l"(p));
    return a;
}

// 16 fp32 -> 16 bf16 (hi or lo residual), packed into two uint4
__device__ __forceinline__ void cvt16(const float4 f[4], bool lo, uint4& o0, uint4& o1)
{
    __nv_bfloat16 h[16];
#pragma unroll
    for (int j = 0; j < 16; j++) {
        float v = ((const float*)f)[j];
        __nv_bfloat16 b = __float2bfloat16(v);
        if (lo) b = __float2bfloat16(v - __bfloat162float(b));
        h[j] = b;
    }
    o0 = ((const uint4*)h)[0];
    o1 = ((const uint4*)h)[1];
}

#define LDSM4(r, a)                                                                     \
    asm volatile("ldmatrix.sync.aligned.m8n8.x4.shared.b16 {%0,%1,%2,%3}, [%4];"        \
                 : "=r"((r)[0]), "=r"((r)[1]), "=r"((r)[2]), "=r"((r)[3]) : "r"(a))

// ---------------- pack B1[n][3K]: blocks [Bh | Bh | Bl] ----------------
__global__ void pack_b1(const float* __restrict__ W_A, const float* __restrict__ W_k,
                        const float* __restrict__ W_beta, const float* __restrict__ B_w)
{
    int idx = blockIdx.x * 256 + threadIdx.x;
    if (idx >= NP * DMODEL) return;
    int n = idx >> 10, k = idx & 1023;
    float v = 0.f;
    if (n < 64)        v = W_A[n * DMODEL + k];
    else if (n < 320)  v = W_k[(size_t)(n - 64) * DMODEL + k];
    else if (n < 322)  v = W_beta[(n - 320) * DMODEL + k];
    else if (n < 450)  v = B_w[(size_t)(n - 322) * DMODEL + k];
    __nv_bfloat16 hi, lo; split_bf16(v, hi, lo);
    __nv_bfloat16* base = g_B1 + (size_t)n * K1EXP;
    base[k] = hi; base[1024 + k] = hi; base[2048 + k] = lo;
}

// ---------------- pack B2[d][384]: k = 12*l + 3*i + s ; (Ch,Ch,Cl), n=l+32i ------
__global__ void pack_b2(const float* __restrict__ C)
{
    int idx = blockIdx.x * 256 + threadIdx.x;
    if (idx >= DMODEL * 128) return;
    int d = idx >> 7, n = idx & 127;
    int l = n & 31, i = n >> 5;
    float v = C[(size_t)d * 128 + n];
    __nv_bfloat16 hi, lo; split_bf16(v, hi, lo);
    __nv_bfloat16* base = g_B2 + (size_t)d * K2EXP + 12 * l + 3 * i;
    base[0] = hi; base[1] = hi; base[2] = lo;
}

// ---------------- bf16 HMMA GEMM (ldmatrix, proven). CONV=1: A is fp32 u, hi/lo split
// happens in-kernel during staging (blocks [hi|lo|hi] all read the same u columns). ----
template <int KTOT, int LDA, int LDB, bool CONV>
__global__ __launch_bounds__(256, 2)
void mma_gemm(const void* __restrict__ Aparam, const __nv_bfloat16* __restrict__ B,
              float* __restrict__ Cout, int ldc,
              const float* __restrict__ uPtr, const float* __restrict__ Dvec)
{
    __shared__ __align__(16) unsigned sA[2][128 * 16];
    __shared__ __align__(16) unsigned sB[2][128 * 16];

    const int tid  = threadIdx.x;
    const int m0   = blockIdx.y * 128;
    const int n0   = blockIdx.x * 128;
    const int lrow = tid >> 1, half = tid & 1;
    const int wid  = tid >> 5, lane = tid & 31;
    const int wm   = wid >> 1, wn = wid & 1;
    const int grp  = lane >> 2, tig = lane & 3;

    const uint4* Ag = nullptr;
    const float4* Au4 = nullptr;
    if constexpr (CONV)
        Au4 = (const float4*)((const float*)Aparam + (size_t)(m0 + lrow) * LDA + half * 16);
    else
        Ag = (const uint4*)Aparam + (size_t)(m0 + lrow) * (LDA / 8) + half * 2;

    const uint4* Bg = (const uint4*)B + (size_t)(n0 + lrow) * (LDB / 8) + half * 2;

    uint32_t soff[2];
#pragma unroll
    for (int q = 0; q < 2; q++)
        soff[q] = (uint32_t)lrow * 64 + ((((uint32_t)(half * 2 + q)) ^ ((lrow >> 1) & 3)) << 4);

    const uint32_t sA0 = smem_u32(&sA[0][0]);
    const uint32_t sB0 = smem_u32(&sB[0][0]);
    uint32_t aOff[2], aS[2];
#pragma unroll
    for (int im = 0; im < 2; im++) {
        int r = wm * 32 + im * 16 + (lane & 15);
        aOff[im] = (uint32_t)r * 64;
        aS[im] = (r >> 1) & 3;
    }
    const uint32_t aC = (uint32_t)(lane >> 4);
    uint32_t bOff[4], bS[4];
#pragma unroll
    for (int p = 0; p < 4; p++) {
        int r = wn * 64 + p * 16 + (lane & 7) + ((lane & 16) >> 1);
        bOff[p] = (uint32_t)r * 64;
        bS[p] = (r >> 1) & 3;
    }
    const uint32_t bC = (uint32_t)((lane >> 3) & 1);

    float acc[2][8][4];
#pragma unroll
    for (int im = 0; im < 2; im++)
#pragma unroll
        for (int in = 0; in < 8; in++)
#pragma unroll
            for (int q = 0; q < 4; q++) acc[im][in][q] = 0.f;

    constexpr int KIT = KTOT / 32;

    uint4 pa0, pa1, pb0, pb1;
    float4 fa[4];
    if constexpr (CONV) {
#pragma unroll
        for (int j = 0; j < 4; j++) fa[j] = Au4[j];          // iter0: cols 0..15
    } else {
        pa0 = Ag[0]; pa1 = Ag[1];
        Ag += 4;
    }
    pb0 = Bg[0]; pb1 = Bg[1];
    Bg += 4;

#define STILE(dst, v0, v1)                                          \
    do {                                                            \
        *(uint4*)((char*)(dst) + soff[0]) = (v0);                   \
        *(uint4*)((char*)(dst) + soff[1]) = (v1);                   \
    } while (0)

    if constexpr (CONV) cvt16(fa, false, pa0, pa1);
    STILE(sA[0], pa0, pa1);
    STILE(sB[0], pb0, pb1);
    __syncthreads();

    for (int it = 0; it < KIT; it++) {
        const int cur = it & 1, nxt = cur ^ 1;
        if (it + 1 < KIT) {
            if constexpr (CONV) {
                const float4* an = Au4 + ((size_t)((it + 1) & 31) << 3);
#pragma unroll
                for (int j = 0; j < 4; j++) fa[j] = an[j];
            } else {
                pa0 = Ag[0]; pa1 = Ag[1];
                Ag += 4;
            }
            pb0 = Bg[0]; pb1 = Bg[1];
            Bg += 4;
        }
        const uint32_t sAc = sA0 + (uint32_t)cur * 8192;
        const uint32_t sBc = sB0 + (uint32_t)cur * 8192;

#pragma unroll
        for (int kk = 0; kk < 2; kk++) {
            unsigned af[2][4], bf[8][2];
#pragma unroll
            for (int im = 0; im < 2; im++) {
                uint32_t ca = (uint32_t)(kk << 1) | aC;
                uint32_t addr = sAc + aOff[im] + ((ca ^ aS[im]) << 4);
                LDSM4(af[im], addr);
            }
#pragma unroll
            for (int p = 0; p < 4; p++) {
                uint32_t cb = (uint32_t)(kk << 1) | bC;
                uint32_t addr = sBc + bOff[p] + ((cb ^ bS[p]) << 4);
                unsigned t[4];
                LDSM4(t, addr);
                bf[2 * p][0] = t[0]; bf[2 * p][1] = t[1];
                bf[2 * p + 1][0] = t[2]; bf[2 * p + 1][1] = t[3];
            }
#pragma unroll
            for (int im = 0; im < 2; im++)
#pragma unroll
                for (int in = 0; in < 8; in++) {
                    float* c = acc[im][in];
                    asm volatile(
                        "mma.sync.aligned.m16n8k16.row.col.f32.bf16.bf16.f32 "
                        "{%0,%1,%2,%3}, {%4,%5,%6,%7}, {%8,%9}, {%0,%1,%2,%3};\n"
                        : "+f"(c[0]), "+f"(c[1]), "+f"(c[2]), "+f"(c[3])
                        : "r"(af[im][0]), "r"(af[im][1]), "r"(af[im][2]), "r"(af[im][3]),
                          "r"(bf[in][0]), "r"(bf[in][1]));
                }
        }

        if (it + 1 < KIT) {
            if constexpr (CONV) cvt16(fa, ((it + 1) >> 5) == 1, pa0, pa1);
            STILE(sA[nxt], pa0, pa1);
            STILE(sB[nxt], pb0, pb1);
            __syncthreads();
        }
    }
#undef STILE

#pragma unroll
    for (int im = 0; im < 2; im++) {
#pragma unroll
        for (int in = 0; in < 8; in++) {
            int row = m0 + wm * 32 + im * 16 + grp;
            int col = n0 + wn * 64 + in * 8 + tig * 2;
            float2 v01 = make_float2(acc[im][in][0], acc[im][in][1]);
            float2 v23 = make_float2(acc[im][in][2], acc[im][in][3]);
            if (uPtr) {
                size_t b0 = (size_t)row * ldc + col;
                size_t b1 = (size_t)(row + 8) * ldc + col;
                v01.x += uPtr[b0] * Dvec[col];
                v01.y += uPtr[b0 + 1] * Dvec[col + 1];
                v23.x += uPtr[b1] * Dvec[col];
                v23.y += uPtr[b1 + 1] * Dvec[col + 1];
            }
            *(float2*)(Cout + (size_t)row * ldc + col)       = v01;
            *(float2*)(Cout + (size_t)(row + 8) * ldc + col) = v23;
        }
    }
}

// ---------------- derive: projections -> scan record (lane layout) + matrix record --------
__global__ void derive_kernel(const float* __restrict__ bA, const float* __restrict__ bk,
                              const float* __restrict__ bbeta, const float* __restrict__ Bb)
{
    const int bt = blockIdx.x;
    const int n = threadIdx.x;               // 0..127
    const int l = n & 31, i = n >> 5;
    const float* p = g_P + (size_t)bt * NP;
    float* rc = g_rec + (size_t)bt * RECW;
    float* r2 = g_rec2 + (size_t)bt * RECW2;

    if (n < 64) {
        float a = fminf(fmaxf(p[n] + bA[n], 0.f), 100.f);
        float S = 1.f / (1.f + 0.01f * a);
        float Dv = 0.1f * a * S;
        rc[4 * l + i]     = S;
        rc[4 * l + 2 + i] = Dv;
        r2[n]      = S;
        r2[64 + n] = Dv;
    }
    float k1 = p[64 + n]  + bk[n];
    float k2 = p[192 + n] + bk[128 + n];
    float Bv = p[322 + n] + Bb[n];

    float s1 = k1 * k1, s2 = k2 * k2, sx = k1 * k2;
#pragma unroll
    for (int off = 16; off; off >>= 1) {
        s1 += __shfl_xor_sync(0xffffffffu, s1, off);
        s2 += __shfl_xor_sync(0xffffffffu, s2, off);
        sx += __shfl_xor_sync(0xffffffffu, sx, off);
    }
    __shared__ float sm[12];
    __shared__ float bc[2];
    int w = n >> 5;
    if ((n & 31) == 0) { sm[w] = s1; sm[4 + w] = s2; sm[8 + w] = sx; }
    __syncthreads();
    if (n == 0) {
        float q1 = sm[0] + sm[1] + sm[2] + sm[3];
        float q2 = sm[4] + sm[5] + sm[6] + sm[7];
        float qx = sm[8] + sm[9] + sm[10] + sm[11];
        float i1 = 1.f / fmaxf(sqrtf(q1), 1e-12f);
        float i2 = 1.f / fmaxf(sqrtf(q2), 1e-12f);
        float be1 = 2.f / (1.f + expf(-(p[320] + bbeta[0])));
        float be2 = 2.f / (1.f + expf(-(p[321] + bbeta[1])));
        float ccv = be1 * qx * i1 * i2;
        rc[512] = be1; rc[513] = be2; rc[514] = ccv;
        r2[384] = be1; r2[385] = be2; r2[386] = ccv;
        bc[0] = i1; bc[1] = i2;
    }
    __syncthreads();
    float k1n = k1 * bc[0];
    float k2n = k2 * bc[1];
    rc[128 + 4 * l + i] = k1n;
    rc[256 + 4 * l + i] = k2n;
    rc[384 + 4 * l + i] = Bv;
    r2[128 + n] = k1n;
    r2[256 + n] = k2n;
}

// ---------------- scan_chunk: R4 loop over one chunk. EMIT=0: p-pass (h0=0, store p_end).
// EMIT=1: output pass (h0 = chunk-start state, emit bf16 Hexp). One warp per chunk. ----
template <int EMIT>
__global__ __launch_bounds__(128)
void scan_chunk()
{
    const int wid = threadIdx.x >> 5;
    const int lane = threadIdx.x & 31;
    const int ch = blockIdx.x * 4 + wid;
    const float4* __restrict__ r4 = (const float4*)g_rec + (size_t)ch * LCH * (RECW / 4);
    __nv_bfloat16* __restrict__ o = g_Hexp + (size_t)ch * LCH * K2EXP;

    float h0 = 0.f, h1 = 0.f, h2 = 0.f, h3 = 0.f;
    if (EMIT && (ch & 15)) {
        float4 hv = *((const float4*)(g_hend + (size_t)(ch - 1) * 128) + lane);
        h0 = hv.x; h1 = hv.y; h2 = hv.z; h3 = hv.w;
    }

    float4 sv[4], av[4], cv[4], bv[4], ev[4];
#pragma unroll
    for (int p = 0; p < 4; p++) {
        const float4* rp = r4 + (size_t)p * (RECW / 4);
        sv[p] = rp[lane];
        av[p] = rp[32 + lane];
        cv[p] = rp[64 + lane];
        bv[p] = rp[96 + lane];
        ev[p] = rp[128];
    }

#pragma unroll 4
    for (int t = 0; t < LCH; t++) {
        const int s = t & 3;
        const float4 S = sv[s], A = av[s], Cv = cv[s], Bv = bv[s], E = ev[s];

        if (t + 4 < LCH) {
            const float4* rp = r4 + (size_t)(t + 4) * (RECW / 4);
            sv[s] = rp[lane];
            av[s] = rp[32 + lane];
            cv[s] = rp[64 + lane];
            bv[s] = rp[96 + lane];
            ev[s] = rp[128];
        }

        float z0 = fmaf(-S.z, h2, S.x * h0);
        float z1 = fmaf(-S.w, h3, S.y * h1);
        float y2 = S.x * fmaf(0.1f, h0, h2);
        float y3 = S.y * fmaf(0.1f, h1, h3);

        float d1 = fmaf(A.x, z0, A.y * z1); d1 = fmaf(A.z, y2, d1); d1 = fmaf(A.w, y3, d1);
        float d2 = fmaf(Cv.x, z0, Cv.y * z1); d2 = fmaf(Cv.z, y2, d2); d2 = fmaf(Cv.w, y3, d2);
#pragma unroll
        for (int off = 16; off; off >>= 1) {
            d1 += __shfl_xor_sync(0xffffffffu, d1, off);
            d2 += __shfl_xor_sync(0xffffffffu, d2, off);
        }

        float a1 = E.x * d1;
        float a2 = E.y * fmaf(-E.z, d1, d2);

        h0 = fmaf(-a2, Cv.x, fmaf(-a1, A.x, z0 + Bv.x));
        h1 = fmaf(-a2, Cv.y, fmaf(-a1, A.y, z1 + Bv.y));
        h2 = fmaf(-a2, Cv.z, fmaf(-a1, A.z, y2 + Bv.z));
        h3 = fmaf(-a2, Cv.w, fmaf(-a1, A.w, y3 + Bv.w));

        if (EMIT) {
            __nv_bfloat16 hh0, hl0, hh1, hl1, hh2, hl2, hh3, hl3;
            split_bf16(h0, hh0, hl0); split_bf16(h1, hh1, hl1);
            split_bf16(h2, hh2, hl2); split_bf16(h3, hh3, hl3);
            unsigned w0 = pack2(hh0, hl0);
            unsigned w1 = pack2(hh0, hh1);
            unsigned w2 = pack2(hl1, hh1);
            unsigned w3 = pack2(hh2, hl2);
            unsigned w4 = pack2(hh2, hh3);
            unsigned w5 = pack2(hl3, hh3);
            uint2* op = (uint2*)(o + (size_t)t * K2EXP) + 3 * lane;
            op[0] = make_uint2(w0, w1);
            op[1] = make_uint2(w2, w3);
            op[2] = make_uint2(w4, w5);
        }
    }

    if (!EMIT)
        *((float4*)(g_pend + (size_t)ch * 128) + lane) = make_float4(h0, h1, h2, h3);
}

// ---------------- chunk_mat: Phi_c = prod of M_t over chunk, on 128 basis columns. --------
__global__ __launch_bounds__(256)
void chunk_mat()
{
    __shared__ __align__(16) float rec[2][4 * RECW2];
    const int ch = blockIdx.y;
    const int tid = threadIdx.x;
    const int col = blockIdx.x * 32 + (tid >> 3);
    const int q = tid & 7;

    const float* rbase = g_rec2 + (size_t)ch * LCH * RECW2;
    constexpr int BLKF = 4 * RECW2;          // 1552 floats per 4-step block

    float zc[8], yc[8];
#pragma unroll
    for (int i = 0; i < 8; i++) {
        int m = 8 * q + i;
        zc[i] = (m == col) ? 1.f : 0.f;
        yc[i] = (m + 64 == col) ? 1.f : 0.f;
    }

    for (int j = tid; j < BLKF; j += 256) rec[0][j] = rbase[j];
    __syncthreads();

    for (int blk = 0; blk < LCH / 4; blk++) {
        const int cur = blk & 1;
        const bool more = (blk + 1 < LCH / 4);
        float pf[7];
        if (more) {
            const float* rn = rbase + (size_t)(blk + 1) * BLKF;
#pragma unroll
            for (int j = 0; j < 7; j++) {
                int idx = tid + 256 * j;
                pf[j] = (idx < BLKF) ? rn[idx] : 0.f;
            }
        }

#pragma unroll
        for (int ts = 0; ts < 4; ts++) {
            const float* rc = &rec[cur][ts * RECW2];
            const float be1 = rc[384], be2 = rc[385], cc = rc[386];

            float Sm[8], Dm[8], K1z[8], K1y[8], K2z[8], K2y[8];
            *(float4*)&Sm[0]  = *(const float4*)(rc + 8 * q);
            *(float4*)&Sm[4]  = *(const float4*)(rc + 8 * q + 4);
            *(float4*)&Dm[0]  = *(const float4*)(rc + 64 + 8 * q);
            *(float4*)&Dm[4]  = *(const float4*)(rc + 64 + 8 * q + 4);
            *(float4*)&K1z[0] = *(const float4*)(rc + 128 + 8 * q);
            *(float4*)&K1z[4] = *(const float4*)(rc + 128 + 8 * q + 4);
            *(float4*)&K1y[0] = *(const float4*)(rc + 192 + 8 * q);
            *(float4*)&K1y[4] = *(const float4*)(rc + 192 + 8 * q + 4);
            *(float4*)&K2z[0] = *(const float4*)(rc + 256 + 8 * q);
            *(float4*)&K2z[4] = *(const float4*)(rc + 256 + 8 * q + 4);
            *(float4*)&K2y[0] = *(const float4*)(rc + 320 + 8 * q);
            *(float4*)&K2y[4] = *(const float4*)(rc + 320 + 8 * q + 4);

            float d1 = 0.f, d2 = 0.f;
#pragma unroll
            for (int i = 0; i < 8; i++) {
                float zn = fmaf(-Dm[i], yc[i], Sm[i] * zc[i]);
                float yn = Sm[i] * fmaf(0.1f, zc[i], yc[i]);
                d1 = fmaf(K1z[i], zn, fmaf(K1y[i], yn, d1));
                d2 = fmaf(K2z[i], zn, fmaf(K2y[i], yn, d2));
                zc[i] = zn; yc[i] = yn;
            }
#pragma unroll
            for (int off = 1; off < 8; off <<= 1) {
                d1 += __shfl_xor_sync(0xffffffffu, d1, off);
                d2 += __shfl_xor_sync(0xffffffffu, d2, off);
            }
            const float a1 = be1 * d1;
            const float a2 = be2 * fmaf(-cc, d1, d2);
#pragma unroll
            for (int i = 0; i < 8; i++) {
                zc[i] = fmaf(-a2, K2z[i], fmaf(-a1, K1z[i], zc[i]));
                yc[i] = fmaf(-a2, K2y[i], fmaf(-a1, K1y[i], yc[i]));
            }
        }

        if (more) {
            __syncthreads();
            float* dst = rec[cur ^ 1];
#pragma unroll
            for (int j = 0; j < 7; j++) {
                int idx = tid + 256 * j;
                if (idx < BLKF) dst[idx] = pf[j];
            }
            __syncthreads();
        }
    }

    float* ph = g_Phi + ((size_t)ch * 128 + col) * 128;
    *(float4*)(ph + 8 * q)          = make_float4(zc[0], zc[1], zc[2], zc[3]);
    *(float4*)(ph + 8 * q + 4)      = make_float4(zc[4], zc[5], zc[6], zc[7]);
    *(float4*)(ph + 64 + 8 * q)     = make_float4(yc[0], yc[1], yc[2], yc[3]);
    *(float4*)(ph + 64 + 8 * q + 4) = make_float4(yc[4], yc[5], yc[6], yc[7]);
}

// ---------------- combine: per batch, sequential over 16 chunks: h = Phi_c h + p_c. ----
__global__ __launch_bounds__(32)
void combine()
{
    const int b = blockIdx.x;
    const int lane = threadIdx.x;
    float a0 = 0.f, a1v = 0.f, a2v = 0.f, a3v = 0.f;

    for (int c = 0; c < 16; c++) {
        const int ch = b * 16 + c;
        const float* Phi = g_Phi + (size_t)ch * 128 * 128;
        float b0 = 0.f, b1 = 0.f, b2 = 0.f, b3 = 0.f;
#pragma unroll
        for (int i = 0; i < 4; i++) {
            float hsrc = (i == 0) ? a0 : (i == 1) ? a1v : (i == 2) ? a2v : a3v;
            for (int cl = 0; cl < 32; cl++) {
                float hc = __shfl_sync(0xffffffffu, hsrc, cl);
                const float* pc = Phi + (size_t)(32 * i + cl) * 128;
                b0 = fmaf(hc, pc[lane], b0);
                b1 = fmaf(hc, pc[32 + lane], b1);
                b2 = fmaf(hc, pc[64 + lane], b2);
                b3 = fmaf(hc, pc[96 + lane], b3);
            }
        }
        const float4 pe = *((const float4*)(g_pend + (size_t)ch * 128) + lane);
        a0 = b0 + pe.x; a1v = b1 + pe.y; a2v = b2 + pe.z; a3v = b3 + pe.w;
        *((float4*)(g_hend + (size_t)ch * 128) + lane) = make_float4(a0, a1v, a2v, a3v);
    }
}

// ---------------- launch ----------------
extern "C" void kernel_launch(void* const* d_in, const int* in_sizes, int n_in,
                              void* d_out, int out_size)
{
    const float* u      = (const float*)d_in[0];
    const float* W_A    = (const float*)d_in[1];
    const float* b_A    = (const float*)d_in[2];
    const float* W_k    = (const float*)d_in[3];
    const float* b_k    = (const float*)d_in[4];
    const float* W_beta = (const float*)d_in[5];
    const float* b_beta = (const float*)d_in[6];
    const float* B_w    = (const float*)d_in[7];
    const float* B_b    = (const float*)d_in[8];
    const float* C      = (const float*)d_in[9];
    const float* D      = (const float*)d_in[10];
    float* out = (float*)d_out;

    pack_b1<<<(NP * DMODEL + 255) / 256, 256>>>(W_A, W_k, W_beta, B_w);
    pack_b2<<<(DMODEL * 128 + 255) / 256, 256>>>(C);

    // GEMM1 (fused A conversion): P[16384 x 512] = split3(u)[16384 x 3072] * B1^T
    {
        __nv_bfloat16* dB; float* dP;
        cudaGetSymbolAddress((void**)&dB, g_B1);
        cudaGetSymbolAddress((void**)&dP, g_P);
        mma_gemm<K1EXP, DMODEL, K1EXP, true><<<dim3(NP / 128, BT / 128), 256>>>(
            u, dB, dP, NP, nullptr, nullptr);
    }

    derive_kernel<<<BT, 128>>>(b_A, b_k, b_beta, B_b);

    // chunked parallel scan
    scan_chunk<0><<<NCH / 4, 128>>>();               // per-chunk particular solutions
    chunk_mat<<<dim3(4, NCH), 256>>>();              // per-chunk transition matrices
    combine<<<BATCH, 32>>>();                        // sequential chunk-level recurrence
    scan_chunk<1><<<NCH / 4, 128>>>();               // emit full outputs

    // GEMM2: out[16384 x 1024] = Hexp[16384 x 384] * B2^T + u * D
    {
        __nv_bfloat16 *dA, *dB;
        cudaGetSymbolAddress((void**)&dA, g_Hexp);
        cudaGetSymbolAddress((void**)&dB, g_B2);
        mma_gemm<K2EXP, K2EXP, K2EXP, false><<<dim3(DMODEL / 128, BT / 128), 256>>>(
            dA, dB, out, DMODEL, u, D);
    }
}

// round 15
// speedup vs baseline: 1.0340x; 1.0340x over previous
#include <cuda_runtime.h>
#include <cuda_bf16.h>
#include <cstdint>
#include <math.h>

#define BATCH   8
#define TT      2048
#define BT      16384      // BATCH*TT
#define DMODEL  1024
#define NP      512        // padded projection columns (450 real)
#define RECW    516        // floats per (b,t) scan record (float4 aligned)
#define RECW2   388        // floats per (b,t) matrix-pass record (S,D,k1,k2,scalars)
#define K1EXP   3072       // 3 * 1024  (bf16 split blocks: [hi, lo, hi])
#define K2EXP   384        // 12 * 32   (interleaved per-lane triplets)
#define LCH     128        // chunk length
#define NCH     (BT / LCH) // 128 chunks (16 per batch)

// ---------------- device scratch (no allocations allowed) ----------------
__device__ __align__(16) __nv_bfloat16 g_Uexp[(size_t)BT * K1EXP];      // A for GEMM1
__device__ __align__(16) __nv_bfloat16 g_B1[(size_t)NP * K1EXP];        // B for GEMM1
__device__ __align__(16) __nv_bfloat16 g_B2[(size_t)DMODEL * K2EXP];    // B for GEMM2
__device__ __align__(16) __nv_bfloat16 g_Hexp[(size_t)BT * K2EXP];      // A for GEMM2
__device__ float g_P[(size_t)BT * NP];                                  // raw projections fp32
__device__ __align__(16) float g_rec[(size_t)BT * RECW];                // scan records (lane layout)
__device__ __align__(16) float g_rec2[(size_t)BT * RECW2];              // matrix-pass records (plain)
__device__ __align__(16) float g_Phi[(size_t)NCH * 128 * 128];          // chunk transition [ch][col][row]
__device__ __align__(16) float g_pend[NCH * 128];                       // chunk particular soln (P layout)
__device__ __align__(16) float g_hend[NCH * 128];                       // chunk end states (P layout)

// ---------------- helpers ----------------
__device__ __forceinline__ void split_bf16(float v, __nv_bfloat16& hi, __nv_bfloat16& lo)
{
    hi = __float2bfloat16(v);
    lo = __float2bfloat16(v - __bfloat162float(hi));
}

__device__ __forceinline__ unsigned pack2(__nv_bfloat16 a, __nv_bfloat16 b)
{
    __nv_bfloat162 p(a, b);
    return *(unsigned*)&p;
}

__device__ __forceinline__ uint32_t smem_u32(const void* p)
{
    uint32_t a;
    asm("{ .reg .u64 t; cvta.to.shared.u64 t, %1; cvt.u32.u64 %0, t; }" : "=r"(a) : "l"(p));
    return a;
}

#define LDSM4(r, a)                                                                     \
    asm volatile("ldmatrix.sync.aligned.m8n8.x4.shared.b16 {%0,%1,%2,%3}, [%4];"        \
                 : "=r"((r)[0]), "=r"((r)[1]), "=r"((r)[2]), "=r"((r)[3]) : "r"(a))

// ---------------- U -> bf16 hi/lo expansion: Uexp[bt][3K] = [hi | lo | hi] ----------------
__global__ void conv_u(const float* __restrict__ u)
{
    size_t i = (size_t)blockIdx.x * 256 + threadIdx.x;
    size_t row = i >> 8;
    int c = (int)(i & 255) * 4;
    float4 v = *(const float4*)(u + row * DMODEL + c);
    __nv_bfloat16 h[4], l[4];
    split_bf16(v.x, h[0], l[0]); split_bf16(v.y, h[1], l[1]);
    split_bf16(v.z, h[2], l[2]); split_bf16(v.w, h[3], l[3]);
    __nv_bfloat16* base = g_Uexp + row * K1EXP;
    *(uint2*)(base + c)        = *(uint2*)h;
    *(uint2*)(base + 1024 + c) = *(uint2*)l;
    *(uint2*)(base + 2048 + c) = *(uint2*)h;
}

// ---------------- pack B1[n][3K]: blocks [Bh | Bh | Bl] ----------------
__global__ void pack_b1(const float* __restrict__ W_A, const float* __restrict__ W_k,
                        const float* __restrict__ W_beta, const float* __restrict__ B_w)
{
    int idx = blockIdx.x * 256 + threadIdx.x;
    if (idx >= NP * DMODEL) return;
    int n = idx >> 10, k = idx & 1023;
    float v = 0.f;
    if (n < 64)        v = W_A[n * DMODEL + k];
    else if (n < 320)  v = W_k[(size_t)(n - 64) * DMODEL + k];
    else if (n < 322)  v = W_beta[(n - 320) * DMODEL + k];
    else if (n < 450)  v = B_w[(size_t)(n - 322) * DMODEL + k];
    __nv_bfloat16 hi, lo; split_bf16(v, hi, lo);
    __nv_bfloat16* base = g_B1 + (size_t)n * K1EXP;
    base[k] = hi; base[1024 + k] = hi; base[2048 + k] = lo;
}

// ---------------- pack B2[d][384]: k = 12*l + 3*i + s ; (Ch,Ch,Cl), n=l+32i ------
__global__ void pack_b2(const float* __restrict__ C)
{
    int idx = blockIdx.x * 256 + threadIdx.x;
    if (idx >= DMODEL * 128) return;
    int d = idx >> 7, n = idx & 127;
    int l = n & 31, i = n >> 5;
    float v = C[(size_t)d * 128 + n];
    __nv_bfloat16 hi, lo; split_bf16(v, hi, lo);
    __nv_bfloat16* base = g_B2 + (size_t)d * K2EXP + 12 * l + 3 * i;
    base[0] = hi; base[1] = hi; base[2] = lo;
}

// ---------------- bf16 HMMA GEMM (R11/R13 ldmatrix version, proven) ----------
template <int KTOT, int LDA, int LDB>
__global__ __launch_bounds__(256)
void mma_gemm(const __nv_bfloat16* __restrict__ A, const __nv_bfloat16* __restrict__ B,
              float* __restrict__ Cout, int ldc,
              const float* __restrict__ uPtr, const float* __restrict__ Dvec)
{
    __shared__ __align__(16) unsigned sA[2][128 * 16];
    __shared__ __align__(16) unsigned sB[2][128 * 16];

    const int tid  = threadIdx.x;
    const int m0   = blockIdx.y * 128;
    const int n0   = blockIdx.x * 128;
    const int lrow = tid >> 1, half = tid & 1;
    const int wid  = tid >> 5, lane = tid & 31;
    const int wm   = wid >> 1, wn = wid & 1;
    const int grp  = lane >> 2, tig = lane & 3;

    const uint4* Ag = (const uint4*)A + (size_t)(m0 + lrow) * (LDA / 8) + half * 2;
    const uint4* Bg = (const uint4*)B + (size_t)(n0 + lrow) * (LDB / 8) + half * 2;

    uint32_t soff[2];
#pragma unroll
    for (int q = 0; q < 2; q++)
        soff[q] = (uint32_t)lrow * 64 + ((((uint32_t)(half * 2 + q)) ^ ((lrow >> 1) & 3)) << 4);

    const uint32_t sA0 = smem_u32(&sA[0][0]);
    const uint32_t sB0 = smem_u32(&sB[0][0]);
    uint32_t aOff[2], aS[2];
#pragma unroll
    for (int im = 0; im < 2; im++) {
        int r = wm * 32 + im * 16 + (lane & 15);
        aOff[im] = (uint32_t)r * 64;
        aS[im] = (r >> 1) & 3;
    }
    const uint32_t aC = (uint32_t)(lane >> 4);
    uint32_t bOff[4], bS[4];
#pragma unroll
    for (int p = 0; p < 4; p++) {
        int r = wn * 64 + p * 16 + (lane & 7) + ((lane & 16) >> 1);
        bOff[p] = (uint32_t)r * 64;
        bS[p] = (r >> 1) & 3;
    }
    const uint32_t bC = (uint32_t)((lane >> 3) & 1);

    float acc[2][8][4];
#pragma unroll
    for (int im = 0; im < 2; im++)
#pragma unroll
        for (int in = 0; in < 8; in++)
#pragma unroll
            for (int q = 0; q < 4; q++) acc[im][in][q] = 0.f;

    constexpr int KIT = KTOT / 32;

    uint4 pa0 = Ag[0], pa1 = Ag[1], pb0 = Bg[0], pb1 = Bg[1];
    Ag += 4; Bg += 4;

#define STILE(dst, v0, v1)                                          \
    do {                                                            \
        *(uint4*)((char*)(dst) + soff[0]) = (v0);                   \
        *(uint4*)((char*)(dst) + soff[1]) = (v1);                   \
    } while (0)

    STILE(sA[0], pa0, pa1);
    STILE(sB[0], pb0, pb1);
    __syncthreads();

    for (int it = 0; it < KIT; it++) {
        const int cur = it & 1, nxt = cur ^ 1;
        if (it + 1 < KIT) {
            pa0 = Ag[0]; pa1 = Ag[1]; pb0 = Bg[0]; pb1 = Bg[1];
            Ag += 4; Bg += 4;
        }
        const uint32_t sAc = sA0 + (uint32_t)cur * 8192;
        const uint32_t sBc = sB0 + (uint32_t)cur * 8192;

#pragma unroll
        for (int kk = 0; kk < 2; kk++) {
            unsigned af[2][4], bf[8][2];
#pragma unroll
            for (int im = 0; im < 2; im++) {
                uint32_t ca = (uint32_t)(kk << 1) | aC;
                uint32_t addr = sAc + aOff[im] + ((ca ^ aS[im]) << 4);
                LDSM4(af[im], addr);
            }
#pragma unroll
            for (int p = 0; p < 4; p++) {
                uint32_t cb = (uint32_t)(kk << 1) | bC;
                uint32_t addr = sBc + bOff[p] + ((cb ^ bS[p]) << 4);
                unsigned t[4];
                LDSM4(t, addr);
                bf[2 * p][0] = t[0]; bf[2 * p][1] = t[1];
                bf[2 * p + 1][0] = t[2]; bf[2 * p + 1][1] = t[3];
            }
#pragma unroll
            for (int im = 0; im < 2; im++)
#pragma unroll
                for (int in = 0; in < 8; in++) {
                    float* c = acc[im][in];
                    asm volatile(
                        "mma.sync.aligned.m16n8k16.row.col.f32.bf16.bf16.f32 "
                        "{%0,%1,%2,%3}, {%4,%5,%6,%7}, {%8,%9}, {%0,%1,%2,%3};\n"
                        : "+f"(c[0]), "+f"(c[1]), "+f"(c[2]), "+f"(c[3])
                        : "r"(af[im][0]), "r"(af[im][1]), "r"(af[im][2]), "r"(af[im][3]),
                          "r"(bf[in][0]), "r"(bf[in][1]));
                }
        }

        if (it + 1 < KIT) {
            STILE(sA[nxt], pa0, pa1);
            STILE(sB[nxt], pb0, pb1);
            __syncthreads();
        }
    }
#undef STILE

#pragma unroll
    for (int im = 0; im < 2; im++) {
#pragma unroll
        for (int in = 0; in < 8; in++) {
            int row = m0 + wm * 32 + im * 16 + grp;
            int col = n0 + wn * 64 + in * 8 + tig * 2;
            float2 v01 = make_float2(acc[im][in][0], acc[im][in][1]);
            float2 v23 = make_float2(acc[im][in][2], acc[im][in][3]);
            if (uPtr) {
                size_t b0 = (size_t)row * ldc + col;
                size_t b1 = (size_t)(row + 8) * ldc + col;
                v01.x += uPtr[b0] * Dvec[col];
                v01.y += uPtr[b0 + 1] * Dvec[col + 1];
                v23.x += uPtr[b1] * Dvec[col];
                v23.y += uPtr[b1 + 1] * Dvec[col + 1];
            }
            *(float2*)(Cout + (size_t)row * ldc + col)       = v01;
            *(float2*)(Cout + (size_t)(row + 8) * ldc + col) = v23;
        }
    }
}

// ---------------- derive: projections -> scan record (lane layout) + matrix record --------
__global__ void derive_kernel(const float* __restrict__ bA, const float* __restrict__ bk,
                              const float* __restrict__ bbeta, const float* __restrict__ Bb)
{
    const int bt = blockIdx.x;
    const int n = threadIdx.x;               // 0..127
    const int l = n & 31, i = n >> 5;
    const float* p = g_P + (size_t)bt * NP;
    float* rc = g_rec + (size_t)bt * RECW;
    float* r2 = g_rec2 + (size_t)bt * RECW2;

    if (n < 64) {
        float a = fminf(fmaxf(p[n] + bA[n], 0.f), 100.f);
        float S = 1.f / (1.f + 0.01f * a);
        float Dv = 0.1f * a * S;
        rc[4 * l + i]     = S;
        rc[4 * l + 2 + i] = Dv;
        r2[n]      = S;
        r2[64 + n] = Dv;
    }
    float k1 = p[64 + n]  + bk[n];
    float k2 = p[192 + n] + bk[128 + n];
    float Bv = p[322 + n] + Bb[n];

    float s1 = k1 * k1, s2 = k2 * k2, sx = k1 * k2;
#pragma unroll
    for (int off = 16; off; off >>= 1) {
        s1 += __shfl_xor_sync(0xffffffffu, s1, off);
        s2 += __shfl_xor_sync(0xffffffffu, s2, off);
        sx += __shfl_xor_sync(0xffffffffu, sx, off);
    }
    __shared__ float sm[12];
    __shared__ float bc[2];
    int w = n >> 5;
    if ((n & 31) == 0) { sm[w] = s1; sm[4 + w] = s2; sm[8 + w] = sx; }
    __syncthreads();
    if (n == 0) {
        float q1 = sm[0] + sm[1] + sm[2] + sm[3];
        float q2 = sm[4] + sm[5] + sm[6] + sm[7];
        float qx = sm[8] + sm[9] + sm[10] + sm[11];
        float i1 = 1.f / fmaxf(sqrtf(q1), 1e-12f);
        float i2 = 1.f / fmaxf(sqrtf(q2), 1e-12f);
        float be1 = 2.f / (1.f + expf(-(p[320] + bbeta[0])));
        float be2 = 2.f / (1.f + expf(-(p[321] + bbeta[1])));
        float ccv = be1 * qx * i1 * i2;
        rc[512] = be1; rc[513] = be2; rc[514] = ccv;
        r2[384] = be1; r2[385] = be2; r2[386] = ccv;
        bc[0] = i1; bc[1] = i2;
    }
    __syncthreads();
    float k1n = k1 * bc[0];
    float k2n = k2 * bc[1];
    rc[128 + 4 * l + i] = k1n;
    rc[256 + 4 * l + i] = k2n;
    rc[384 + 4 * l + i] = Bv;
    r2[128 + n] = k1n;
    r2[256 + n] = k2n;
}

// ---------------- scan_chunk: R4 loop over one chunk. EMIT=0: p-pass (h0=0, store p_end).
// EMIT=1: output pass (h0 = chunk-start state, emit bf16 Hexp). One warp per chunk. ----
template <int EMIT>
__global__ __launch_bounds__(128)
void scan_chunk()
{
    const int wid = threadIdx.x >> 5;
    const int lane = threadIdx.x & 31;
    const int ch = blockIdx.x * 4 + wid;
    const float4* __restrict__ r4 = (const float4*)g_rec + (size_t)ch * LCH * (RECW / 4);
    __nv_bfloat16* __restrict__ o = g_Hexp + (size_t)ch * LCH * K2EXP;

    float h0 = 0.f, h1 = 0.f, h2 = 0.f, h3 = 0.f;
    if (EMIT && (ch & 15)) {
        float4 hv = *((const float4*)(g_hend + (size_t)(ch - 1) * 128) + lane);
        h0 = hv.x; h1 = hv.y; h2 = hv.z; h3 = hv.w;
    }

    float4 sv[4], av[4], cv[4], bv[4], ev[4];
#pragma unroll
    for (int p = 0; p < 4; p++) {
        const float4* rp = r4 + (size_t)p * (RECW / 4);
        sv[p] = rp[lane];
        av[p] = rp[32 + lane];
        cv[p] = rp[64 + lane];
        bv[p] = rp[96 + lane];
        ev[p] = rp[128];
    }

#pragma unroll 4
    for (int t = 0; t < LCH; t++) {
        const int s = t & 3;
        const float4 S = sv[s], A = av[s], Cv = cv[s], Bv = bv[s], E = ev[s];

        if (t + 4 < LCH) {
            const float4* rp = r4 + (size_t)(t + 4) * (RECW / 4);
            sv[s] = rp[lane];
            av[s] = rp[32 + lane];
            cv[s] = rp[64 + lane];
            bv[s] = rp[96 + lane];
            ev[s] = rp[128];
        }

        float z0 = fmaf(-S.z, h2, S.x * h0);
        float z1 = fmaf(-S.w, h3, S.y * h1);
        float y2 = S.x * fmaf(0.1f, h0, h2);
        float y3 = S.y * fmaf(0.1f, h1, h3);

        float d1 = fmaf(A.x, z0, A.y * z1); d1 = fmaf(A.z, y2, d1); d1 = fmaf(A.w, y3, d1);
        float d2 = fmaf(Cv.x, z0, Cv.y * z1); d2 = fmaf(Cv.z, y2, d2); d2 = fmaf(Cv.w, y3, d2);
#pragma unroll
        for (int off = 16; off; off >>= 1) {
            d1 += __shfl_xor_sync(0xffffffffu, d1, off);
            d2 += __shfl_xor_sync(0xffffffffu, d2, off);
        }

        float a1 = E.x * d1;
        float a2 = E.y * fmaf(-E.z, d1, d2);

        h0 = fmaf(-a2, Cv.x, fmaf(-a1, A.x, z0 + Bv.x));
        h1 = fmaf(-a2, Cv.y, fmaf(-a1, A.y, z1 + Bv.y));
        h2 = fmaf(-a2, Cv.z, fmaf(-a1, A.z, y2 + Bv.z));
        h3 = fmaf(-a2, Cv.w, fmaf(-a1, A.w, y3 + Bv.w));

        if (EMIT) {
            __nv_bfloat16 hh0, hl0, hh1, hl1, hh2, hl2, hh3, hl3;
            split_bf16(h0, hh0, hl0); split_bf16(h1, hh1, hl1);
            split_bf16(h2, hh2, hl2); split_bf16(h3, hh3, hl3);
            unsigned w0 = pack2(hh0, hl0);
            unsigned w1 = pack2(hh0, hh1);
            unsigned w2 = pack2(hl1, hh1);
            unsigned w3 = pack2(hh2, hl2);
            unsigned w4 = pack2(hh2, hh3);
            unsigned w5 = pack2(hl3, hh3);
            uint2* op = (uint2*)(o + (size_t)t * K2EXP) + 3 * lane;
            op[0] = make_uint2(w0, w1);
            op[1] = make_uint2(w2, w3);
            op[2] = make_uint2(w4, w5);
        }
    }

    if (!EMIT)
        *((float4*)(g_pend + (size_t)ch * 128) + lane) = make_float4(h0, h1, h2, h3);
}

// ---------------- chunk_mat: Phi_c = prod of M_t over chunk, on 128 basis columns. --------
__global__ __launch_bounds__(256)
void chunk_mat()
{
    __shared__ __align__(16) float rec[2][4 * RECW2];
    const int ch = blockIdx.y;
    const int tid = threadIdx.x;
    const int col = blockIdx.x * 32 + (tid >> 3);
    const int q = tid & 7;

    const float* rbase = g_rec2 + (size_t)ch * LCH * RECW2;
    constexpr int BLKF = 4 * RECW2;          // 1552 floats per 4-step block

    float zc[8], yc[8];
#pragma unroll
    for (int i = 0; i < 8; i++) {
        int m = 8 * q + i;
        zc[i] = (m == col) ? 1.f : 0.f;
        yc[i] = (m + 64 == col) ? 1.f : 0.f;
    }

    for (int j = tid; j < BLKF; j += 256) rec[0][j] = rbase[j];
    __syncthreads();

    for (int blk = 0; blk < LCH / 4; blk++) {
        const int cur = blk & 1;
        const bool more = (blk + 1 < LCH / 4);
        float pf[7];
        if (more) {
            const float* rn = rbase + (size_t)(blk + 1) * BLKF;
#pragma unroll
            for (int j = 0; j < 7; j++) {
                int idx = tid + 256 * j;
                pf[j] = (idx < BLKF) ? rn[idx] : 0.f;
            }
        }

#pragma unroll
        for (int ts = 0; ts < 4; ts++) {
            const float* rc = &rec[cur][ts * RECW2];
            const float be1 = rc[384], be2 = rc[385], cc = rc[386];

            float Sm[8], Dm[8], K1z[8], K1y[8], K2z[8], K2y[8];
            *(float4*)&Sm[0]  = *(const float4*)(rc + 8 * q);
            *(float4*)&Sm[4]  = *(const float4*)(rc + 8 * q + 4);
            *(float4*)&Dm[0]  = *(const float4*)(rc + 64 + 8 * q);
            *(float4*)&Dm[4]  = *(const float4*)(rc + 64 + 8 * q + 4);
            *(float4*)&K1z[0] = *(const float4*)(rc + 128 + 8 * q);
            *(float4*)&K1z[4] = *(const float4*)(rc + 128 + 8 * q + 4);
            *(float4*)&K1y[0] = *(const float4*)(rc + 192 + 8 * q);
            *(float4*)&K1y[4] = *(const float4*)(rc + 192 + 8 * q + 4);
            *(float4*)&K2z[0] = *(const float4*)(rc + 256 + 8 * q);
            *(float4*)&K2z[4] = *(const float4*)(rc + 256 + 8 * q + 4);
            *(float4*)&K2y[0] = *(const float4*)(rc + 320 + 8 * q);
            *(float4*)&K2y[4] = *(const float4*)(rc + 320 + 8 * q + 4);

            float d1 = 0.f, d2 = 0.f;
#pragma unroll
            for (int i = 0; i < 8; i++) {
                float zn = fmaf(-Dm[i], yc[i], Sm[i] * zc[i]);
                float yn = Sm[i] * fmaf(0.1f, zc[i], yc[i]);
                d1 = fmaf(K1z[i], zn, fmaf(K1y[i], yn, d1));
                d2 = fmaf(K2z[i], zn, fmaf(K2y[i], yn, d2));
                zc[i] = zn; yc[i] = yn;
            }
#pragma unroll
            for (int off = 1; off < 8; off <<= 1) {
                d1 += __shfl_xor_sync(0xffffffffu, d1, off);
                d2 += __shfl_xor_sync(0xffffffffu, d2, off);
            }
            const float a1 = be1 * d1;
            const float a2 = be2 * fmaf(-cc, d1, d2);
#pragma unroll
            for (int i = 0; i < 8; i++) {
                zc[i] = fmaf(-a2, K2z[i], fmaf(-a1, K1z[i], zc[i]));
                yc[i] = fmaf(-a2, K2y[i], fmaf(-a1, K1y[i], yc[i]));
            }
        }

        if (more) {
            __syncthreads();
            float* dst = rec[cur ^ 1];
#pragma unroll
            for (int j = 0; j < 7; j++) {
                int idx = tid + 256 * j;
                if (idx < BLKF) dst[idx] = pf[j];
            }
            __syncthreads();
        }
    }

    float* ph = g_Phi + ((size_t)ch * 128 + col) * 128;
    *(float4*)(ph + 8 * q)          = make_float4(zc[0], zc[1], zc[2], zc[3]);
    *(float4*)(ph + 8 * q + 4)      = make_float4(zc[4], zc[5], zc[6], zc[7]);
    *(float4*)(ph + 64 + 8 * q)     = make_float4(yc[0], yc[1], yc[2], yc[3]);
    *(float4*)(ph + 64 + 8 * q + 4) = make_float4(yc[4], yc[5], yc[6], yc[7]);
}

// ---------------- combine v2: 128 threads per batch. Thread tid owns logical row tid;
// h in smem; Phi[col*128+tid] reads fully coalesced, unroll-16 for MLP. pend/hend stay
// in the float4-lane layout via m(n) = 4*(n&31) + (n>>5). ----
__global__ __launch_bounds__(128)
void combine()
{
    __shared__ float hs[128];
    const int b = blockIdx.x;
    const int tid = threadIdx.x;
    const int mi = 4 * (tid & 31) + (tid >> 5);

    hs[tid] = 0.f;
    __syncthreads();

    for (int c = 0; c < 16; c++) {
        const int ch = b * 16 + c;
        const float* __restrict__ Phi = g_Phi + (size_t)ch * 128 * 128;
        float y = 0.f;
#pragma unroll 16
        for (int col = 0; col < 128; col++)
            y = fmaf(Phi[(size_t)col * 128 + tid], hs[col], y);
        y += g_pend[(size_t)ch * 128 + mi];
        __syncthreads();
        hs[tid] = y;
        g_hend[(size_t)ch * 128 + mi] = y;
        __syncthreads();
    }
}

// ---------------- launch ----------------
extern "C" void kernel_launch(void* const* d_in, const int* in_sizes, int n_in,
                              void* d_out, int out_size)
{
    const float* u      = (const float*)d_in[0];
    const float* W_A    = (const float*)d_in[1];
    const float* b_A    = (const float*)d_in[2];
    const float* W_k    = (const float*)d_in[3];
    const float* b_k    = (const float*)d_in[4];
    const float* W_beta = (const float*)d_in[5];
    const float* b_beta = (const float*)d_in[6];
    const float* B_w    = (const float*)d_in[7];
    const float* B_b    = (const float*)d_in[8];
    const float* C      = (const float*)d_in[9];
    const float* D      = (const float*)d_in[10];
    float* out = (float*)d_out;

    pack_b1<<<(NP * DMODEL + 255) / 256, 256>>>(W_A, W_k, W_beta, B_w);
    pack_b2<<<(DMODEL * 128 + 255) / 256, 256>>>(C);
    conv_u<<<(BT * (DMODEL / 4)) / 256, 256>>>(u);

    // GEMM1: P[16384 x 512] = Uexp[16384 x 3072] * B1^T
    {
        __nv_bfloat16 *dA, *dB; float* dP;
        cudaGetSymbolAddress((void**)&dA, g_Uexp);
        cudaGetSymbolAddress((void**)&dB, g_B1);
        cudaGetSymbolAddress((void**)&dP, g_P);
        mma_gemm<K1EXP, K1EXP, K1EXP><<<dim3(NP / 128, BT / 128), 256>>>(
            dA, dB, dP, NP, nullptr, nullptr);
    }

    derive_kernel<<<BT, 128>>>(b_A, b_k, b_beta, B_b);

    // chunked parallel scan
    scan_chunk<0><<<NCH / 4, 128>>>();               // per-chunk particular solutions
    chunk_mat<<<dim3(4, NCH), 256>>>();              // per-chunk transition matrices
    combine<<<BATCH, 128>>>();                       // chunk-level recurrence (128 thr/batch)
    scan_chunk<1><<<NCH / 4, 128>>>();               // emit full outputs

    // GEMM2: out[16384 x 1024] = Hexp[16384 x 384] * B2^T + u * D
    {
        __nv_bfloat16 *dA, *dB;
        cudaGetSymbolAddress((void**)&dA, g_Hexp);
        cudaGetSymbolAddress((void**)&dB, g_B2);
        mma_gemm<K2EXP, K2EXP, K2EXP><<<dim3(DMODEL / 128, BT / 128), 256>>>(
            dA, dB, out, DMODEL, u, D);
    }
}

// round 16
// speedup vs baseline: 1.1123x; 1.0758x over previous
#include <cuda_runtime.h>
#include <cuda_bf16.h>
#include <cstdint>
#include <math.h>

#define BATCH   8
#define TT      2048
#define BT      16384      // BATCH*TT
#define DMODEL  1024
#define NP      512        // padded projection columns (450 real)
#define RECW    516        // floats per (b,t) scan record (float4 aligned)
#define RECW2   388        // floats per (b,t) matrix-pass record
#define K1SPL   2048       // 2 * 1024 (bf16 split blocks: [hi | lo])
#define K2EXP   384        // 12 * 32  (interleaved per-lane triplets)
#define LCH     128        // chunk length
#define NCH     (BT / LCH) // 128 chunks (16 per batch)

// ---------------- device scratch (no allocations allowed) ----------------
__device__ __align__(16) __nv_bfloat16 g_Uexp[(size_t)BT * K1SPL];      // A for GEMM1 [hi|lo]
__device__ __align__(16) __nv_bfloat16 g_B1[(size_t)NP * K1SPL];        // B for GEMM1 [hi|lo]
__device__ __align__(16) __nv_bfloat16 g_B2[(size_t)DMODEL * K2EXP];    // B for GEMM2
__device__ __align__(16) __nv_bfloat16 g_Hexp[(size_t)BT * K2EXP];      // A for GEMM2
__device__ float g_P[(size_t)BT * NP];                                  // raw projections fp32
__device__ __align__(16) float g_rec[(size_t)BT * RECW];                // scan records (lane layout)
__device__ __align__(16) float g_rec2[(size_t)BT * RECW2];              // matrix-pass records (plain)
__device__ __align__(16) float g_Phi[(size_t)NCH * 128 * 128];          // chunk transition [ch][col][row]
__device__ __align__(16) float g_pend[NCH * 128];                       // chunk particular soln (P layout)
__device__ __align__(16) float g_hend[NCH * 128];                       // chunk end states (P layout)

// ---------------- helpers ----------------
__device__ __forceinline__ void split_bf16(float v, __nv_bfloat16& hi, __nv_bfloat16& lo)
{
    hi = __float2bfloat16(v);
    lo = __float2bfloat16(v - __bfloat162float(hi));
}

__device__ __forceinline__ unsigned pack2(__nv_bfloat16 a, __nv_bfloat16 b)
{
    __nv_bfloat162 p(a, b);
    return *(unsigned*)&p;
}

__device__ __forceinline__ uint32_t smem_u32(const void* p)
{
    uint32_t a;
    asm("{ .reg .u64 t; cvta.to.shared.u64 t, %1; cvt.u32.u64 %0, t; }" : "=r"(a) : "l"(p));
    return a;
}

#define LDSM4(r, a)                                                                     \
    asm volatile("ldmatrix.sync.aligned.m8n8.x4.shared.b16 {%0,%1,%2,%3}, [%4];"        \
                 : "=r"((r)[0]), "=r"((r)[1]), "=r"((r)[2]), "=r"((r)[3]) : "r"(a))

#define CPASYNC(sm, gp)                                                                 \
    asm volatile("cp.async.cg.shared.global [%0], [%1], 16;" :: "r"(sm), "l"(gp))
#define CPCOMMIT() asm volatile("cp.async.commit_group;" ::: "memory")

#define MMA16(afr, bfr)                                                                 \
    do {                                                                                \
        _Pragma("unroll")                                                               \
        for (int im = 0; im < 2; im++)                                                  \
            _Pragma("unroll")                                                           \
            for (int in = 0; in < 8; in++) {                                            \
                float* c = acc[im][in];                                                 \
                asm volatile(                                                           \
                    "mma.sync.aligned.m16n8k16.row.col.f32.bf16.bf16.f32 "              \
                    "{%0,%1,%2,%3}, {%4,%5,%6,%7}, {%8,%9}, {%0,%1,%2,%3};\n"           \
                    : "+f"(c[0]), "+f"(c[1]), "+f"(c[2]), "+f"(c[3])                    \
                    : "r"((afr)[im][0]), "r"((afr)[im][1]),                             \
                      "r"((afr)[im][2]), "r"((afr)[im][3]),                             \
                      "r"((bfr)[in][0]), "r"((bfr)[in][1]));                            \
            }                                                                           \
    } while (0)

// ---------------- U -> bf16 hi/lo: Uexp[bt][2048] = [hi | lo] ----------------
__global__ void conv_u(const float* __restrict__ u)
{
    size_t i = (size_t)blockIdx.x * 256 + threadIdx.x;
    size_t row = i >> 8;
    int c = (int)(i & 255) * 4;
    float4 v = *(const float4*)(u + row * DMODEL + c);
    __nv_bfloat16 h[4], l[4];
    split_bf16(v.x, h[0], l[0]); split_bf16(v.y, h[1], l[1]);
    split_bf16(v.z, h[2], l[2]); split_bf16(v.w, h[3], l[3]);
    __nv_bfloat16* base = g_Uexp + row * K1SPL;
    *(uint2*)(base + c)        = *(uint2*)h;
    *(uint2*)(base + 1024 + c) = *(uint2*)l;
}

// ---------------- pack B1[n][2048]: [hi | lo] ----------------
__global__ void pack_b1(const float* __restrict__ W_A, const float* __restrict__ W_k,
                        const float* __restrict__ W_beta, const float* __restrict__ B_w)
{
    int idx = blockIdx.x * 256 + threadIdx.x;
    if (idx >= NP * DMODEL) return;
    int n = idx >> 10, k = idx & 1023;
    float v = 0.f;
    if (n < 64)        v = W_A[n * DMODEL + k];
    else if (n < 320)  v = W_k[(size_t)(n - 64) * DMODEL + k];
    else if (n < 322)  v = W_beta[(n - 320) * DMODEL + k];
    else if (n < 450)  v = B_w[(size_t)(n - 322) * DMODEL + k];
    __nv_bfloat16 hi, lo; split_bf16(v, hi, lo);
    __nv_bfloat16* base = g_B1 + (size_t)n * K1SPL;
    base[k] = hi; base[1024 + k] = lo;
}

// ---------------- pack B2[d][384]: k = 12*l + 3*i + s ; (Ch,Ch,Cl), n=l+32i ------
__global__ void pack_b2(const float* __restrict__ C)
{
    int idx = blockIdx.x * 256 + threadIdx.x;
    if (idx >= DMODEL * 128) return;
    int d = idx >> 7, n = idx & 127;
    int l = n & 31, i = n >> 5;
    float v = C[(size_t)d * 128 + n];
    __nv_bfloat16 hi, lo; split_bf16(v, hi, lo);
    __nv_bfloat16* base = g_B2 + (size_t)d * K2EXP + 12 * l + 3 * i;
    base[0] = hi; base[1] = hi; base[2] = lo;
}

// ---------------- GEMM1: split-dedup bf16 HMMA. 128x128 tile, 32 K-slices of 32.
// Per slice: stage 4 unique tiles (Ah,Al,Bh,Bl) via cp.async; 3 MMA groups reuse frags:
// AhBh, AlBh (reuse Bh), AhBl (reuse Ah). 33% less smem traffic than 3-block layout. ----
__global__ __launch_bounds__(256, 2)
void mma_gemm1(const __nv_bfloat16* __restrict__ A, const __nv_bfloat16* __restrict__ B,
               float* __restrict__ Cout)
{
    extern __shared__ __align__(16) unsigned smem[];
    // layout (bytes): buf b at b*32768; Ah +0, Al +8192, Bh +16384, Bl +24576

    const int tid  = threadIdx.x;
    const int m0   = blockIdx.y * 128;
    const int n0   = blockIdx.x * 128;
    const int row  = tid >> 1, half = tid & 1;
    const int wid  = tid >> 5, lane = tid & 31;
    const int wm   = wid >> 1, wn = wid & 1;
    const int grp  = lane >> 2, tig = lane & 3;

    const uint32_t sbase = smem_u32(smem);

    uint32_t soff[2];
#pragma unroll
    for (int q = 0; q < 2; q++)
        soff[q] = (uint32_t)row * 64 + ((((uint32_t)(half * 2 + q)) ^ ((row >> 1) & 3)) << 4);

    const __nv_bfloat16* gAh = A + (size_t)(m0 + row) * K1SPL + half * 16;
    const __nv_bfloat16* gBh = B + (size_t)(n0 + row) * K1SPL + half * 16;

    uint32_t aOff[2], aS[2];
#pragma unroll
    for (int im = 0; im < 2; im++) {
        int r = wm * 32 + im * 16 + (lane & 15);
        aOff[im] = (uint32_t)r * 64;
        aS[im] = (r >> 1) & 3;
    }
    const uint32_t aC = (uint32_t)(lane >> 4);
    uint32_t bOff[4], bS[4];
#pragma unroll
    for (int p = 0; p < 4; p++) {
        int r = wn * 64 + p * 16 + (lane & 7) + ((lane & 16) >> 1);
        bOff[p] = (uint32_t)r * 64;
        bS[p] = (r >> 1) & 3;
    }
    const uint32_t bC = (uint32_t)((lane >> 3) & 1);

    float acc[2][8][4];
#pragma unroll
    for (int im = 0; im < 2; im++)
#pragma unroll
        for (int in = 0; in < 8; in++)
#pragma unroll
            for (int q = 0; q < 4; q++) acc[im][in][q] = 0.f;

#define STAGE(s, b)                                                                     \
    do {                                                                                \
        uint32_t s0 = sbase + (uint32_t)(b) * 32768u;                                   \
        const __nv_bfloat16* ah = gAh + (s) * 32;                                       \
        const __nv_bfloat16* bh = gBh + (s) * 32;                                       \
        CPASYNC(s0 + soff[0],          ah);                                             \
        CPASYNC(s0 + soff[1],          ah + 8);                                         \
        CPASYNC(s0 + 8192 + soff[0],   ah + 1024);                                      \
        CPASYNC(s0 + 8192 + soff[1],   ah + 1032);                                      \
        CPASYNC(s0 + 16384 + soff[0],  bh);                                             \
        CPASYNC(s0 + 16384 + soff[1],  bh + 8);                                         \
        CPASYNC(s0 + 24576 + soff[0],  bh + 1024);                                      \
        CPASYNC(s0 + 24576 + soff[1],  bh + 1032);                                      \
        CPCOMMIT();                                                                     \
    } while (0)

    STAGE(0, 0);

    for (int s = 0; s < 32; s++) {
        const int cur = s & 1;
        if (s + 1 < 32) {
            STAGE(s + 1, cur ^ 1);
            asm volatile("cp.async.wait_group 1;" ::: "memory");
        } else {
            asm volatile("cp.async.wait_group 0;" ::: "memory");
        }
        __syncthreads();

        const uint32_t bufb = sbase + (uint32_t)cur * 32768u;

#pragma unroll
        for (int kk = 0; kk < 2; kk++) {
            unsigned afh[2][4], afl[2][4], bff[8][2];
            const uint32_t ca = (uint32_t)(kk << 1) | aC;
            const uint32_t cb = (uint32_t)(kk << 1) | bC;
#pragma unroll
            for (int im = 0; im < 2; im++)
                LDSM4(afh[im], bufb + aOff[im] + ((ca ^ aS[im]) << 4));
#pragma unroll
            for (int p = 0; p < 4; p++) {
                unsigned t[4];
                LDSM4(t, bufb + 16384 + bOff[p] + ((cb ^ bS[p]) << 4));
                bff[2 * p][0] = t[0]; bff[2 * p][1] = t[1];
                bff[2 * p + 1][0] = t[2]; bff[2 * p + 1][1] = t[3];
            }
            MMA16(afh, bff);                       // Ah * Bh
#pragma unroll
            for (int im = 0; im < 2; im++)
                LDSM4(afl[im], bufb + 8192 + aOff[im] + ((ca ^ aS[im]) << 4));
            MMA16(afl, bff);                       // Al * Bh
#pragma unroll
            for (int p = 0; p < 4; p++) {
                unsigned t[4];
                LDSM4(t, bufb + 24576 + bOff[p] + ((cb ^ bS[p]) << 4));
                bff[2 * p][0] = t[0]; bff[2 * p][1] = t[1];
                bff[2 * p + 1][0] = t[2]; bff[2 * p + 1][1] = t[3];
            }
            MMA16(afh, bff);                       // Ah * Bl
        }
        __syncthreads();
    }
#undef STAGE

#pragma unroll
    for (int im = 0; im < 2; im++) {
#pragma unroll
        for (int in = 0; in < 8; in++) {
            int r = m0 + wm * 32 + im * 16 + grp;
            int c = n0 + wn * 64 + in * 8 + tig * 2;
            *(float2*)(Cout + (size_t)r * NP + c)       = make_float2(acc[im][in][0], acc[im][in][1]);
            *(float2*)(Cout + (size_t)(r + 8) * NP + c) = make_float2(acc[im][in][2], acc[im][in][3]);
        }
    }
}

// ---------------- generic bf16 HMMA GEMM (R11/R15, proven) — used for GEMM2 ----------
template <int KTOT, int LDA, int LDB>
__global__ __launch_bounds__(256)
void mma_gemm(const __nv_bfloat16* __restrict__ A, const __nv_bfloat16* __restrict__ B,
              float* __restrict__ Cout, int ldc,
              const float* __restrict__ uPtr, const float* __restrict__ Dvec)
{
    __shared__ __align__(16) unsigned sA[2][128 * 16];
    __shared__ __align__(16) unsigned sB[2][128 * 16];

    const int tid  = threadIdx.x;
    const int m0   = blockIdx.y * 128;
    const int n0   = blockIdx.x * 128;
    const int lrow = tid >> 1, half = tid & 1;
    const int wid  = tid >> 5, lane = tid & 31;
    const int wm   = wid >> 1, wn = wid & 1;
    const int grp  = lane >> 2, tig = lane & 3;

    const uint4* Ag = (const uint4*)A + (size_t)(m0 + lrow) * (LDA / 8) + half * 2;
    const uint4* Bg = (const uint4*)B + (size_t)(n0 + lrow) * (LDB / 8) + half * 2;

    uint32_t soff[2];
#pragma unroll
    for (int q = 0; q < 2; q++)
        soff[q] = (uint32_t)lrow * 64 + ((((uint32_t)(half * 2 + q)) ^ ((lrow >> 1) & 3)) << 4);

    const uint32_t sA0 = smem_u32(&sA[0][0]);
    const uint32_t sB0 = smem_u32(&sB[0][0]);
    uint32_t aOff[2], aS[2];
#pragma unroll
    for (int im = 0; im < 2; im++) {
        int r = wm * 32 + im * 16 + (lane & 15);
        aOff[im] = (uint32_t)r * 64;
        aS[im] = (r >> 1) & 3;
    }
    const uint32_t aC = (uint32_t)(lane >> 4);
    uint32_t bOff[4], bS[4];
#pragma unroll
    for (int p = 0; p < 4; p++) {
        int r = wn * 64 + p * 16 + (lane & 7) + ((lane & 16) >> 1);
        bOff[p] = (uint32_t)r * 64;
        bS[p] = (r >> 1) & 3;
    }
    const uint32_t bC = (uint32_t)((lane >> 3) & 1);

    float acc[2][8][4];
#pragma unroll
    for (int im = 0; im < 2; im++)
#pragma unroll
        for (int in = 0; in < 8; in++)
#pragma unroll
            for (int q = 0; q < 4; q++) acc[im][in][q] = 0.f;

    constexpr int KIT = KTOT / 32;

    uint4 pa0 = Ag[0], pa1 = Ag[1], pb0 = Bg[0], pb1 = Bg[1];
    Ag += 4; Bg += 4;

#define STILE(dst, v0, v1)                                          \
    do {                                                            \
        *(uint4*)((char*)(dst) + soff[0]) = (v0);                   \
        *(uint4*)((char*)(dst) + soff[1]) = (v1);                   \
    } while (0)

    STILE(sA[0], pa0, pa1);
    STILE(sB[0], pb0, pb1);
    __syncthreads();

    for (int it = 0; it < KIT; it++) {
        const int cur = it & 1, nxt = cur ^ 1;
        if (it + 1 < KIT) {
            pa0 = Ag[0]; pa1 = Ag[1]; pb0 = Bg[0]; pb1 = Bg[1];
            Ag += 4; Bg += 4;
        }
        const uint32_t sAc = sA0 + (uint32_t)cur * 8192;
        const uint32_t sBc = sB0 + (uint32_t)cur * 8192;

#pragma unroll
        for (int kk = 0; kk < 2; kk++) {
            unsigned af[2][4], bf[8][2];
#pragma unroll
            for (int im = 0; im < 2; im++) {
                uint32_t ca = (uint32_t)(kk << 1) | aC;
                uint32_t addr = sAc + aOff[im] + ((ca ^ aS[im]) << 4);
                LDSM4(af[im], addr);
            }
#pragma unroll
            for (int p = 0; p < 4; p++) {
                uint32_t cb = (uint32_t)(kk << 1) | bC;
                uint32_t addr = sBc + bOff[p] + ((cb ^ bS[p]) << 4);
                unsigned t[4];
                LDSM4(t, addr);
                bf[2 * p][0] = t[0]; bf[2 * p][1] = t[1];
                bf[2 * p + 1][0] = t[2]; bf[2 * p + 1][1] = t[3];
            }
            MMA16(af, bf);
        }

        if (it + 1 < KIT) {
            STILE(sA[nxt], pa0, pa1);
            STILE(sB[nxt], pb0, pb1);
            __syncthreads();
        }
    }
#undef STILE

#pragma unroll
    for (int im = 0; im < 2; im++) {
#pragma unroll
        for (int in = 0; in < 8; in++) {
            int row = m0 + wm * 32 + im * 16 + grp;
            int col = n0 + wn * 64 + in * 8 + tig * 2;
            float2 v01 = make_float2(acc[im][in][0], acc[im][in][1]);
            float2 v23 = make_float2(acc[im][in][2], acc[im][in][3]);
            if (uPtr) {
                size_t b0 = (size_t)row * ldc + col;
                size_t b1 = (size_t)(row + 8) * ldc + col;
                v01.x += uPtr[b0] * Dvec[col];
                v01.y += uPtr[b0 + 1] * Dvec[col + 1];
                v23.x += uPtr[b1] * Dvec[col];
                v23.y += uPtr[b1 + 1] * Dvec[col + 1];
            }
            *(float2*)(Cout + (size_t)row * ldc + col)       = v01;
            *(float2*)(Cout + (size_t)(row + 8) * ldc + col) = v23;
        }
    }
}

// ---------------- derive: projections -> scan record (lane layout) + matrix record --------
__global__ void derive_kernel(const float* __restrict__ bA, const float* __restrict__ bk,
                              const float* __restrict__ bbeta, const float* __restrict__ Bb)
{
    const int bt = blockIdx.x;
    const int n = threadIdx.x;               // 0..127
    const int l = n & 31, i = n >> 5;
    const float* p = g_P + (size_t)bt * NP;
    float* rc = g_rec + (size_t)bt * RECW;
    float* r2 = g_rec2 + (size_t)bt * RECW2;

    if (n < 64) {
        float a = fminf(fmaxf(p[n] + bA[n], 0.f), 100.f);
        float S = 1.f / (1.f + 0.01f * a);
        float Dv = 0.1f * a * S;
        rc[4 * l + i]     = S;
        rc[4 * l + 2 + i] = Dv;
        r2[n]      = S;
        r2[64 + n] = Dv;
    }
    float k1 = p[64 + n]  + bk[n];
    float k2 = p[192 + n] + bk[128 + n];
    float Bv = p[322 + n] + Bb[n];

    float s1 = k1 * k1, s2 = k2 * k2, sx = k1 * k2;
#pragma unroll
    for (int off = 16; off; off >>= 1) {
        s1 += __shfl_xor_sync(0xffffffffu, s1, off);
        s2 += __shfl_xor_sync(0xffffffffu, s2, off);
        sx += __shfl_xor_sync(0xffffffffu, sx, off);
    }
    __shared__ float sm[12];
    __shared__ float bc[2];
    int w = n >> 5;
    if ((n & 31) == 0) { sm[w] = s1; sm[4 + w] = s2; sm[8 + w] = sx; }
    __syncthreads();
    if (n == 0) {
        float q1 = sm[0] + sm[1] + sm[2] + sm[3];
        float q2 = sm[4] + sm[5] + sm[6] + sm[7];
        float qx = sm[8] + sm[9] + sm[10] + sm[11];
        float i1 = 1.f / fmaxf(sqrtf(q1), 1e-12f);
        float i2 = 1.f / fmaxf(sqrtf(q2), 1e-12f);
        float be1 = 2.f / (1.f + expf(-(p[320] + bbeta[0])));
        float be2 = 2.f / (1.f + expf(-(p[321] + bbeta[1])));
        float ccv = be1 * qx * i1 * i2;
        rc[512] = be1; rc[513] = be2; rc[514] = ccv;
        r2[384] = be1; r2[385] = be2; r2[386] = ccv;
        bc[0] = i1; bc[1] = i2;
    }
    __syncthreads();
    float k1n = k1 * bc[0];
    float k2n = k2 * bc[1];
    rc[128 + 4 * l + i] = k1n;
    rc[256 + 4 * l + i] = k2n;
    rc[384 + 4 * l + i] = Bv;
    r2[128 + n] = k1n;
    r2[256 + n] = k2n;
}

// ---------------- scan_chunk (R15, proven) ----------
template <int EMIT>
__global__ __launch_bounds__(128)
void scan_chunk()
{
    const int wid = threadIdx.x >> 5;
    const int lane = threadIdx.x & 31;
    const int ch = blockIdx.x * 4 + wid;
    const float4* __restrict__ r4 = (const float4*)g_rec + (size_t)ch * LCH * (RECW / 4);
    __nv_bfloat16* __restrict__ o = g_Hexp + (size_t)ch * LCH * K2EXP;

    float h0 = 0.f, h1 = 0.f, h2 = 0.f, h3 = 0.f;
    if (EMIT && (ch & 15)) {
        float4 hv = *((const float4*)(g_hend + (size_t)(ch - 1) * 128) + lane);
        h0 = hv.x; h1 = hv.y; h2 = hv.z; h3 = hv.w;
    }

    float4 sv[4], av[4], cv[4], bv[4], ev[4];
#pragma unroll
    for (int p = 0; p < 4; p++) {
        const float4* rp = r4 + (size_t)p * (RECW / 4);
        sv[p] = rp[lane];
        av[p] = rp[32 + lane];
        cv[p] = rp[64 + lane];
        bv[p] = rp[96 + lane];
        ev[p] = rp[128];
    }

#pragma unroll 4
    for (int t = 0; t < LCH; t++) {
        const int s = t & 3;
        const float4 S = sv[s], A = av[s], Cv = cv[s], Bv = bv[s], E = ev[s];

        if (t + 4 < LCH) {
            const float4* rp = r4 + (size_t)(t + 4) * (RECW / 4);
            sv[s] = rp[lane];
            av[s] = rp[32 + lane];
            cv[s] = rp[64 + lane];
            bv[s] = rp[96 + lane];
            ev[s] = rp[128];
        }

        float z0 = fmaf(-S.z, h2, S.x * h0);
        float z1 = fmaf(-S.w, h3, S.y * h1);
        float y2 = S.x * fmaf(0.1f, h0, h2);
        float y3 = S.y * fmaf(0.1f, h1, h3);

        float d1 = fmaf(A.x, z0, A.y * z1); d1 = fmaf(A.z, y2, d1); d1 = fmaf(A.w, y3, d1);
        float d2 = fmaf(Cv.x, z0, Cv.y * z1); d2 = fmaf(Cv.z, y2, d2); d2 = fmaf(Cv.w, y3, d2);
#pragma unroll
        for (int off = 16; off; off >>= 1) {
            d1 += __shfl_xor_sync(0xffffffffu, d1, off);
            d2 += __shfl_xor_sync(0xffffffffu, d2, off);
        }

        float a1 = E.x * d1;
        float a2 = E.y * fmaf(-E.z, d1, d2);

        h0 = fmaf(-a2, Cv.x, fmaf(-a1, A.x, z0 + Bv.x));
        h1 = fmaf(-a2, Cv.y, fmaf(-a1, A.y, z1 + Bv.y));
        h2 = fmaf(-a2, Cv.z, fmaf(-a1, A.z, y2 + Bv.z));
        h3 = fmaf(-a2, Cv.w, fmaf(-a1, A.w, y3 + Bv.w));

        if (EMIT) {
            __nv_bfloat16 hh0, hl0, hh1, hl1, hh2, hl2, hh3, hl3;
            split_bf16(h0, hh0, hl0); split_bf16(h1, hh1, hl1);
            split_bf16(h2, hh2, hl2); split_bf16(h3, hh3, hl3);
            unsigned w0 = pack2(hh0, hl0);
            unsigned w1 = pack2(hh0, hh1);
            unsigned w2 = pack2(hl1, hh1);
            unsigned w3 = pack2(hh2, hl2);
            unsigned w4 = pack2(hh2, hh3);
            unsigned w5 = pack2(hl3, hh3);
            uint2* op = (uint2*)(o + (size_t)t * K2EXP) + 3 * lane;
            op[0] = make_uint2(w0, w1);
            op[1] = make_uint2(w2, w3);
            op[2] = make_uint2(w4, w5);
        }
    }

    if (!EMIT)
        *((float4*)(g_pend + (size_t)ch * 128) + lane) = make_float4(h0, h1, h2, h3);
}

// ---------------- chunk_mat (R15, proven) ----------
__global__ __launch_bounds__(256)
void chunk_mat()
{
    __shared__ __align__(16) float rec[2][4 * RECW2];
    const int ch = blockIdx.y;
    const int tid = threadIdx.x;
    const int col = blockIdx.x * 32 + (tid >> 3);
    const int q = tid & 7;

    const float* rbase = g_rec2 + (size_t)ch * LCH * RECW2;
    constexpr int BLKF = 4 * RECW2;

    float zc[8], yc[8];
#pragma unroll
    for (int i = 0; i < 8; i++) {
        int m = 8 * q + i;
        zc[i] = (m == col) ? 1.f : 0.f;
        yc[i] = (m + 64 == col) ? 1.f : 0.f;
    }

    for (int j = tid; j < BLKF; j += 256) rec[0][j] = rbase[j];
    __syncthreads();

    for (int blk = 0; blk < LCH / 4; blk++) {
        const int cur = blk & 1;
        const bool more = (blk + 1 < LCH / 4);
        float pf[7];
        if (more) {
            const float* rn = rbase + (size_t)(blk + 1) * BLKF;
#pragma unroll
            for (int j = 0; j < 7; j++) {
                int idx = tid + 256 * j;
                pf[j] = (idx < BLKF) ? rn[idx] : 0.f;
            }
        }

#pragma unroll
        for (int ts = 0; ts < 4; ts++) {
            const float* rc = &rec[cur][ts * RECW2];
            const float be1 = rc[384], be2 = rc[385], cc = rc[386];

            float Sm[8], Dm[8], K1z[8], K1y[8], K2z[8], K2y[8];
            *(float4*)&Sm[0]  = *(const float4*)(rc + 8 * q);
            *(float4*)&Sm[4]  = *(const float4*)(rc + 8 * q + 4);
            *(float4*)&Dm[0]  = *(const float4*)(rc + 64 + 8 * q);
            *(float4*)&Dm[4]  = *(const float4*)(rc + 64 + 8 * q + 4);
            *(float4*)&K1z[0] = *(const float4*)(rc + 128 + 8 * q);
            *(float4*)&K1z[4] = *(const float4*)(rc + 128 + 8 * q + 4);
            *(float4*)&K1y[0] = *(const float4*)(rc + 192 + 8 * q);
            *(float4*)&K1y[4] = *(const float4*)(rc + 192 + 8 * q + 4);
            *(float4*)&K2z[0] = *(const float4*)(rc + 256 + 8 * q);
            *(float4*)&K2z[4] = *(const float4*)(rc + 256 + 8 * q + 4);
            *(float4*)&K2y[0] = *(const float4*)(rc + 320 + 8 * q);
            *(float4*)&K2y[4] = *(const float4*)(rc + 320 + 8 * q + 4);

            float d1 = 0.f, d2 = 0.f;
#pragma unroll
            for (int i = 0; i < 8; i++) {
                float zn = fmaf(-Dm[i], yc[i], Sm[i] * zc[i]);
                float yn = Sm[i] * fmaf(0.1f, zc[i], yc[i]);
                d1 = fmaf(K1z[i], zn, fmaf(K1y[i], yn, d1));
                d2 = fmaf(K2z[i], zn, fmaf(K2y[i], yn, d2));
                zc[i] = zn; yc[i] = yn;
            }
#pragma unroll
            for (int off = 1; off < 8; off <<= 1) {
                d1 += __shfl_xor_sync(0xffffffffu, d1, off);
                d2 += __shfl_xor_sync(0xffffffffu, d2, off);
            }
            const float a1 = be1 * d1;
            const float a2 = be2 * fmaf(-cc, d1, d2);
#pragma unroll
            for (int i = 0; i < 8; i++) {
                zc[i] = fmaf(-a2, K2z[i], fmaf(-a1, K1z[i], zc[i]));
                yc[i] = fmaf(-a2, K2y[i], fmaf(-a1, K1y[i], yc[i]));
            }
        }

        if (more) {
            __syncthreads();
            float* dst = rec[cur ^ 1];
#pragma unroll
            for (int j = 0; j < 7; j++) {
                int idx = tid + 256 * j;
                if (idx < BLKF) dst[idx] = pf[j];
            }
            __syncthreads();
        }
    }

    float* ph = g_Phi + ((size_t)ch * 128 + col) * 128;
    *(float4*)(ph + 8 * q)          = make_float4(zc[0], zc[1], zc[2], zc[3]);
    *(float4*)(ph + 8 * q + 4)      = make_float4(zc[4], zc[5], zc[6], zc[7]);
    *(float4*)(ph + 64 + 8 * q)     = make_float4(yc[0], yc[1], yc[2], yc[3]);
    *(float4*)(ph + 64 + 8 * q + 4) = make_float4(yc[4], yc[5], yc[6], yc[7]);
}

// ---------------- combine (R15, proven) ----------
__global__ __launch_bounds__(128)
void combine()
{
    __shared__ float hs[128];
    const int b = blockIdx.x;
    const int tid = threadIdx.x;
    const int mi = 4 * (tid & 31) + (tid >> 5);

    hs[tid] = 0.f;
    __syncthreads();

    for (int c = 0; c < 16; c++) {
        const int ch = b * 16 + c;
        const float* __restrict__ Phi = g_Phi + (size_t)ch * 128 * 128;
        float y = 0.f;
#pragma unroll 16
        for (int col = 0; col < 128; col++)
            y = fmaf(Phi[(size_t)col * 128 + tid], hs[col], y);
        y += g_pend[(size_t)ch * 128 + mi];
        __syncthreads();
        hs[tid] = y;
        g_hend[(size_t)ch * 128 + mi] = y;
        __syncthreads();
    }
}

// ---------------- launch ----------------
extern "C" void kernel_launch(void* const* d_in, const int* in_sizes, int n_in,
                              void* d_out, int out_size)
{
    const float* u      = (const float*)d_in[0];
    const float* W_A    = (const float*)d_in[1];
    const float* b_A    = (const float*)d_in[2];
    const float* W_k    = (const float*)d_in[3];
    const float* b_k    = (const float*)d_in[4];
    const float* W_beta = (const float*)d_in[5];
    const float* b_beta = (const float*)d_in[6];
    const float* B_w    = (const float*)d_in[7];
    const float* B_b    = (const float*)d_in[8];
    const float* C      = (const float*)d_in[9];
    const float* D      = (const float*)d_in[10];
    float* out = (float*)d_out;

    static bool attr_done = false;
    if (!attr_done) {
        cudaFuncSetAttribute(mma_gemm1, cudaFuncAttributeMaxDynamicSharedMemorySize, 65536);
        attr_done = true;
    }

    pack_b1<<<(NP * DMODEL + 255) / 256, 256>>>(W_A, W_k, W_beta, B_w);
    pack_b2<<<(DMODEL * 128 + 255) / 256, 256>>>(C);
    conv_u<<<(BT * (DMODEL / 4)) / 256, 256>>>(u);

    // GEMM1: P[16384 x 512] = [Uh|Ul][16384 x 2048] x-dedup B1^T
    {
        __nv_bfloat16 *dA, *dB; float* dP;
        cudaGetSymbolAddress((void**)&dA, g_Uexp);
        cudaGetSymbolAddress((void**)&dB, g_B1);
        cudaGetSymbolAddress((void**)&dP, g_P);
        mma_gemm1<<<dim3(NP / 128, BT / 128), 256, 65536>>>(dA, dB, dP);
    }

    derive_kernel<<<BT, 128>>>(b_A, b_k, b_beta, B_b);

    // chunked parallel scan
    scan_chunk<0><<<NCH / 4, 128>>>();
    chunk_mat<<<dim3(4, NCH), 256>>>();
    combine<<<BATCH, 128>>>();
    scan_chunk<1><<<NCH / 4, 128>>>();

    // GEMM2: out[16384 x 1024] = Hexp[16384 x 384] * B2^T + u * D
    {
        __nv_bfloat16 *dA, *dB;
        cudaGetSymbolAddress((void**)&dA, g_Hexp);
        cudaGetSymbolAddress((void**)&dB, g_B2);
        mma_gemm<K2EXP, K2EXP, K2EXP><<<dim3(DMODEL / 128, BT / 128), 256>>>(
            dA, dB, out, DMODEL, u, D);
    }
}

// round 17
// speedup vs baseline: 1.1817x; 1.0623x over previous
#include <cuda_runtime.h>
#include <cuda_bf16.h>
#include <cstdint>
#include <math.h>

#define BATCH   8
#define TT      2048
#define BT      16384      // BATCH*TT
#define DMODEL  1024
#define NP      512        // padded projection columns (450 real)
#define RECW    516        // floats per (b,t) scan record (float4 aligned)
#define RECW2   388        // floats per (b,t) matrix-pass record
#define K1SPL   1024       // half-width of GEMM1 split operands [hi | lo]
#define K2SPL   128        // half-width of GEMM2 split operands [hi | lo]
#define LCH     128        // chunk length
#define NCH     (BT / LCH) // 128 chunks (16 per batch)

// ---------------- device scratch (no allocations allowed) ----------------
__device__ __align__(16) __nv_bfloat16 g_Uexp[(size_t)BT * 2 * K1SPL];  // A GEMM1 [hi|lo]
__device__ __align__(16) __nv_bfloat16 g_B1[(size_t)NP * 2 * K1SPL];    // B GEMM1 [hi|lo]
__device__ __align__(16) __nv_bfloat16 g_B2[(size_t)DMODEL * 2 * K2SPL];// B GEMM2 [Ch|Cl] perm
__device__ __align__(16) __nv_bfloat16 g_Hexp[(size_t)BT * 2 * K2SPL];  // A GEMM2 [hi|lo] perm
__device__ float g_P[(size_t)BT * NP];                                  // raw projections fp32
__device__ __align__(16) float g_rec[(size_t)BT * RECW];                // scan records (lane layout)
__device__ __align__(16) float g_rec2[(size_t)BT * RECW2];              // matrix-pass records (plain)
__device__ __align__(16) float g_Phi[(size_t)NCH * 128 * 128];          // chunk transition [ch][col][row]
__device__ __align__(16) float g_pend[NCH * 128];                       // chunk particular soln (P layout)
__device__ __align__(16) float g_hend[NCH * 128];                       // chunk end states (P layout)

// ---------------- helpers ----------------
__device__ __forceinline__ void split_bf16(float v, __nv_bfloat16& hi, __nv_bfloat16& lo)
{
    hi = __float2bfloat16(v);
    lo = __float2bfloat16(v - __bfloat162float(hi));
}

__device__ __forceinline__ unsigned pack2(__nv_bfloat16 a, __nv_bfloat16 b)
{
    __nv_bfloat162 p(a, b);
    return *(unsigned*)&p;
}

__device__ __forceinline__ uint32_t smem_u32(const void* p)
{
    uint32_t a;
    asm("{ .reg .u64 t; cvta.to.shared.u64 t, %1; cvt.u32.u64 %0, t; }" : "=r"(a) : "l"(p));
    return a;
}

#define LDSM4(r, a)                                                                     \
    asm volatile("ldmatrix.sync.aligned.m8n8.x4.shared.b16 {%0,%1,%2,%3}, [%4];"        \
                 : "=r"((r)[0]), "=r"((r)[1]), "=r"((r)[2]), "=r"((r)[3]) : "r"(a))

#define CPASYNC(sm, gp)                                                                 \
    asm volatile("cp.async.cg.shared.global [%0], [%1], 16;" :: "r"(sm), "l"(gp))
#define CPCOMMIT() asm volatile("cp.async.commit_group;" ::: "memory")

#define MMA16(afr, bfr)                                                                 \
    do {                                                                                \
        _Pragma("unroll")                                                               \
        for (int im = 0; im < 2; im++)                                                  \
            _Pragma("unroll")                                                           \
            for (int in = 0; in < 8; in++) {                                            \
                float* c = acc[im][in];                                                 \
                asm volatile(                                                           \
                    "mma.sync.aligned.m16n8k16.row.col.f32.bf16.bf16.f32 "              \
                    "{%0,%1,%2,%3}, {%4,%5,%6,%7}, {%8,%9}, {%0,%1,%2,%3};\n"           \
                    : "+f"(c[0]), "+f"(c[1]), "+f"(c[2]), "+f"(c[3])                    \
                    : "r"((afr)[im][0]), "r"((afr)[im][1]),                             \
                      "r"((afr)[im][2]), "r"((afr)[im][3]),                             \
                      "r"((bfr)[in][0]), "r"((bfr)[in][1]));                            \
            }                                                                           \
    } while (0)

// ---------------- U -> bf16 hi/lo: Uexp[bt][2048] = [hi | lo] ----------------
__global__ void conv_u(const float* __restrict__ u)
{
    size_t i = (size_t)blockIdx.x * 256 + threadIdx.x;
    size_t row = i >> 8;
    int c = (int)(i & 255) * 4;
    float4 v = *(const float4*)(u + row * DMODEL + c);
    __nv_bfloat16 h[4], l[4];
    split_bf16(v.x, h[0], l[0]); split_bf16(v.y, h[1], l[1]);
    split_bf16(v.z, h[2], l[2]); split_bf16(v.w, h[3], l[3]);
    __nv_bfloat16* base = g_Uexp + row * 2 * K1SPL;
    *(uint2*)(base + c)         = *(uint2*)h;
    *(uint2*)(base + K1SPL + c) = *(uint2*)l;
}

// ---------------- pack B1[n][2048]: [hi | lo] ----------------
__global__ void pack_b1(const float* __restrict__ W_A, const float* __restrict__ W_k,
                        const float* __restrict__ W_beta, const float* __restrict__ B_w)
{
    int idx = blockIdx.x * 256 + threadIdx.x;
    if (idx >= NP * DMODEL) return;
    int n = idx >> 10, k = idx & 1023;
    float v = 0.f;
    if (n < 64)        v = W_A[n * DMODEL + k];
    else if (n < 320)  v = W_k[(size_t)(n - 64) * DMODEL + k];
    else if (n < 322)  v = W_beta[(n - 320) * DMODEL + k];
    else if (n < 450)  v = B_w[(size_t)(n - 322) * DMODEL + k];
    __nv_bfloat16 hi, lo; split_bf16(v, hi, lo);
    __nv_bfloat16* base = g_B1 + (size_t)n * 2 * K1SPL;
    base[k] = hi; base[K1SPL + k] = lo;
}

// ---------------- pack B2[d][256]: [Ch | Cl], perm col 4l+i <-> n=l+32i ------
__global__ void pack_b2(const float* __restrict__ C)
{
    int idx = blockIdx.x * 256 + threadIdx.x;
    if (idx >= DMODEL * 128) return;
    int d = idx >> 7, n = idx & 127;
    int l = n & 31, i = n >> 5;
    float v = C[(size_t)d * 128 + n];
    __nv_bfloat16 hi, lo; split_bf16(v, hi, lo);
    __nv_bfloat16* base = g_B2 + (size_t)d * 2 * K2SPL;
    base[4 * l + i] = hi;
    base[K2SPL + 4 * l + i] = lo;
}

// ---------------- split-dedup bf16 HMMA GEMM. 128x128 tile; NSLICE K-slices of 32.
// Per slice stage 4 unique tiles (Ah,Al,Bh,Bl); 3 MMA groups reuse frags.
// 3-stage cp.async ring, ONE syncthreads per slice (prefetch dist 2). ----
template <int KSPL, int NSLICE, bool EPI>
__global__ __launch_bounds__(256, 2)
void mma_dedup(const __nv_bfloat16* __restrict__ A, const __nv_bfloat16* __restrict__ B,
               float* __restrict__ Cout, int ldc,
               const float* __restrict__ uPtr, const float* __restrict__ Dvec)
{
    extern __shared__ __align__(16) unsigned smem[];
    // stage st at st*32768 bytes; Ah +0, Al +8192, Bh +16384, Bl +24576

    const int tid  = threadIdx.x;
    const int m0   = blockIdx.y * 128;
    const int n0   = blockIdx.x * 128;
    const int row  = tid >> 1, half = tid & 1;
    const int wid  = tid >> 5, lane = tid & 31;
    const int wm   = wid >> 1, wn = wid & 1;
    const int grp  = lane >> 2, tig = lane & 3;

    const uint32_t sbase = smem_u32(smem);

    uint32_t soff[2];
#pragma unroll
    for (int q = 0; q < 2; q++)
        soff[q] = (uint32_t)row * 64 + ((((uint32_t)(half * 2 + q)) ^ ((row >> 1) & 3)) << 4);

    const __nv_bfloat16* gA = A + (size_t)(m0 + row) * (2 * KSPL) + half * 16;
    const __nv_bfloat16* gB = B + (size_t)(n0 + row) * (2 * KSPL) + half * 16;

    uint32_t aOff[2], aS[2];
#pragma unroll
    for (int im = 0; im < 2; im++) {
        int r = wm * 32 + im * 16 + (lane & 15);
        aOff[im] = (uint32_t)r * 64;
        aS[im] = (r >> 1) & 3;
    }
    const uint32_t aC = (uint32_t)(lane >> 4);
    uint32_t bOff[4], bS[4];
#pragma unroll
    for (int p = 0; p < 4; p++) {
        int r = wn * 64 + p * 16 + (lane & 7) + ((lane & 16) >> 1);
        bOff[p] = (uint32_t)r * 64;
        bS[p] = (r >> 1) & 3;
    }
    const uint32_t bC = (uint32_t)((lane >> 3) & 1);

    float acc[2][8][4];
#pragma unroll
    for (int im = 0; im < 2; im++)
#pragma unroll
        for (int in = 0; in < 8; in++)
#pragma unroll
            for (int q = 0; q < 4; q++) acc[im][in][q] = 0.f;

#define STAGE(s, st)                                                                    \
    do {                                                                                \
        uint32_t s0 = sbase + (uint32_t)(st) * 32768u;                                  \
        const __nv_bfloat16* ah = gA + (s) * 32;                                        \
        const __nv_bfloat16* bh = gB + (s) * 32;                                        \
        CPASYNC(s0 + soff[0],          ah);                                             \
        CPASYNC(s0 + soff[1],          ah + 8);                                         \
        CPASYNC(s0 + 8192 + soff[0],   ah + KSPL);                                      \
        CPASYNC(s0 + 8192 + soff[1],   ah + KSPL + 8);                                  \
        CPASYNC(s0 + 16384 + soff[0],  bh);                                             \
        CPASYNC(s0 + 16384 + soff[1],  bh + 8);                                         \
        CPASYNC(s0 + 24576 + soff[0],  bh + KSPL);                                      \
        CPASYNC(s0 + 24576 + soff[1],  bh + KSPL + 8);                                  \
        CPCOMMIT();                                                                     \
    } while (0)

    STAGE(0, 0);
    STAGE(1, 1);

    for (int s = 0; s < NSLICE; s++) {
        if (s + 1 < NSLICE)
            asm volatile("cp.async.wait_group 1;" ::: "memory");
        else
            asm volatile("cp.async.wait_group 0;" ::: "memory");
        __syncthreads();   // stage s visible to all; iter s-1 reads complete

        if (s + 2 < NSLICE)
            STAGE(s + 2, (s + 2) % 3);

        const uint32_t bufb = sbase + (uint32_t)(s % 3) * 32768u;

#pragma unroll
        for (int kk = 0; kk < 2; kk++) {
            unsigned afh[2][4], afl[2][4], bff[8][2];
            const uint32_t ca = (uint32_t)(kk << 1) | aC;
            const uint32_t cb = (uint32_t)(kk << 1) | bC;
#pragma unroll
            for (int im = 0; im < 2; im++)
                LDSM4(afh[im], bufb + aOff[im] + ((ca ^ aS[im]) << 4));
#pragma unroll
            for (int p = 0; p < 4; p++) {
                unsigned t[4];
                LDSM4(t, bufb + 16384 + bOff[p] + ((cb ^ bS[p]) << 4));
                bff[2 * p][0] = t[0]; bff[2 * p][1] = t[1];
                bff[2 * p + 1][0] = t[2]; bff[2 * p + 1][1] = t[3];
            }
            MMA16(afh, bff);                       // Ah * Bh
#pragma unroll
            for (int im = 0; im < 2; im++)
                LDSM4(afl[im], bufb + 8192 + aOff[im] + ((ca ^ aS[im]) << 4));
            MMA16(afl, bff);                       // Al * Bh
#pragma unroll
            for (int p = 0; p < 4; p++) {
                unsigned t[4];
                LDSM4(t, bufb + 24576 + bOff[p] + ((cb ^ bS[p]) << 4));
                bff[2 * p][0] = t[0]; bff[2 * p][1] = t[1];
                bff[2 * p + 1][0] = t[2]; bff[2 * p + 1][1] = t[3];
            }
            MMA16(afh, bff);                       // Ah * Bl
        }
    }
#undef STAGE

#pragma unroll
    for (int im = 0; im < 2; im++) {
#pragma unroll
        for (int in = 0; in < 8; in++) {
            int r = m0 + wm * 32 + im * 16 + grp;
            int c = n0 + wn * 64 + in * 8 + tig * 2;
            float2 v01 = make_float2(acc[im][in][0], acc[im][in][1]);
            float2 v23 = make_float2(acc[im][in][2], acc[im][in][3]);
            if (EPI) {
                size_t b0 = (size_t)r * ldc + c;
                size_t b1 = (size_t)(r + 8) * ldc + c;
                v01.x += uPtr[b0] * Dvec[c];
                v01.y += uPtr[b0 + 1] * Dvec[c + 1];
                v23.x += uPtr[b1] * Dvec[c];
                v23.y += uPtr[b1 + 1] * Dvec[c + 1];
            }
            *(float2*)(Cout + (size_t)r * ldc + c)       = v01;
            *(float2*)(Cout + (size_t)(r + 8) * ldc + c) = v23;
        }
    }
}

// ---------------- derive: projections -> scan record (lane layout) + matrix record --------
__global__ void derive_kernel(const float* __restrict__ bA, const float* __restrict__ bk,
                              const float* __restrict__ bbeta, const float* __restrict__ Bb)
{
    const int bt = blockIdx.x;
    const int n = threadIdx.x;               // 0..127
    const int l = n & 31, i = n >> 5;
    const float* p = g_P + (size_t)bt * NP;
    float* rc = g_rec + (size_t)bt * RECW;
    float* r2 = g_rec2 + (size_t)bt * RECW2;

    if (n < 64) {
        float a = fminf(fmaxf(p[n] + bA[n], 0.f), 100.f);
        float S = 1.f / (1.f + 0.01f * a);
        float Dv = 0.1f * a * S;
        rc[4 * l + i]     = S;
        rc[4 * l + 2 + i] = Dv;
        r2[n]      = S;
        r2[64 + n] = Dv;
    }
    float k1 = p[64 + n]  + bk[n];
    float k2 = p[192 + n] + bk[128 + n];
    float Bv = p[322 + n] + Bb[n];

    float s1 = k1 * k1, s2 = k2 * k2, sx = k1 * k2;
#pragma unroll
    for (int off = 16; off; off >>= 1) {
        s1 += __shfl_xor_sync(0xffffffffu, s1, off);
        s2 += __shfl_xor_sync(0xffffffffu, s2, off);
        sx += __shfl_xor_sync(0xffffffffu, sx, off);
    }
    __shared__ float sm[12];
    __shared__ float bc[2];
    int w = n >> 5;
    if ((n & 31) == 0) { sm[w] = s1; sm[4 + w] = s2; sm[8 + w] = sx; }
    __syncthreads();
    if (n == 0) {
        float q1 = sm[0] + sm[1] + sm[2] + sm[3];
        float q2 = sm[4] + sm[5] + sm[6] + sm[7];
        float qx = sm[8] + sm[9] + sm[10] + sm[11];
        float i1 = 1.f / fmaxf(sqrtf(q1), 1e-12f);
        float i2 = 1.f / fmaxf(sqrtf(q2), 1e-12f);
        float be1 = 2.f / (1.f + expf(-(p[320] + bbeta[0])));
        float be2 = 2.f / (1.f + expf(-(p[321] + bbeta[1])));
        float ccv = be1 * qx * i1 * i2;
        rc[512] = be1; rc[513] = be2; rc[514] = ccv;
        r2[384] = be1; r2[385] = be2; r2[386] = ccv;
        bc[0] = i1; bc[1] = i2;
    }
    __syncthreads();
    float k1n = k1 * bc[0];
    float k2n = k2 * bc[1];
    rc[128 + 4 * l + i] = k1n;
    rc[256 + 4 * l + i] = k2n;
    rc[384 + 4 * l + i] = Bv;
    r2[128 + n] = k1n;
    r2[256 + n] = k2n;
}

// ---------------- scan_chunk: EMIT=0 p-pass; EMIT=1 emits Hexp [hi|lo] perm layout. ----
template <int EMIT>
__global__ __launch_bounds__(128)
void scan_chunk()
{
    const int wid = threadIdx.x >> 5;
    const int lane = threadIdx.x & 31;
    const int ch = blockIdx.x * 4 + wid;
    const float4* __restrict__ r4 = (const float4*)g_rec + (size_t)ch * LCH * (RECW / 4);
    __nv_bfloat16* __restrict__ o = g_Hexp + (size_t)ch * LCH * 2 * K2SPL;

    float h0 = 0.f, h1 = 0.f, h2 = 0.f, h3 = 0.f;
    if (EMIT && (ch & 15)) {
        float4 hv = *((const float4*)(g_hend + (size_t)(ch - 1) * 128) + lane);
        h0 = hv.x; h1 = hv.y; h2 = hv.z; h3 = hv.w;
    }

    float4 sv[4], av[4], cv[4], bv[4], ev[4];
#pragma unroll
    for (int p = 0; p < 4; p++) {
        const float4* rp = r4 + (size_t)p * (RECW / 4);
        sv[p] = rp[lane];
        av[p] = rp[32 + lane];
        cv[p] = rp[64 + lane];
        bv[p] = rp[96 + lane];
        ev[p] = rp[128];
    }

#pragma unroll 4
    for (int t = 0; t < LCH; t++) {
        const int s = t & 3;
        const float4 S = sv[s], A = av[s], Cv = cv[s], Bv = bv[s], E = ev[s];

        if (t + 4 < LCH) {
            const float4* rp = r4 + (size_t)(t + 4) * (RECW / 4);
            sv[s] = rp[lane];
            av[s] = rp[32 + lane];
            cv[s] = rp[64 + lane];
            bv[s] = rp[96 + lane];
            ev[s] = rp[128];
        }

        float z0 = fmaf(-S.z, h2, S.x * h0);
        float z1 = fmaf(-S.w, h3, S.y * h1);
        float y2 = S.x * fmaf(0.1f, h0, h2);
        float y3 = S.y * fmaf(0.1f, h1, h3);

        float d1 = fmaf(A.x, z0, A.y * z1); d1 = fmaf(A.z, y2, d1); d1 = fmaf(A.w, y3, d1);
        float d2 = fmaf(Cv.x, z0, Cv.y * z1); d2 = fmaf(Cv.z, y2, d2); d2 = fmaf(Cv.w, y3, d2);
#pragma unroll
        for (int off = 16; off; off >>= 1) {
            d1 += __shfl_xor_sync(0xffffffffu, d1, off);
            d2 += __shfl_xor_sync(0xffffffffu, d2, off);
        }

        float a1 = E.x * d1;
        float a2 = E.y * fmaf(-E.z, d1, d2);

        h0 = fmaf(-a2, Cv.x, fmaf(-a1, A.x, z0 + Bv.x));
        h1 = fmaf(-a2, Cv.y, fmaf(-a1, A.y, z1 + Bv.y));
        h2 = fmaf(-a2, Cv.z, fmaf(-a1, A.z, y2 + Bv.z));
        h3 = fmaf(-a2, Cv.w, fmaf(-a1, A.w, y3 + Bv.w));

        if (EMIT) {
            __nv_bfloat16 hh0, hl0, hh1, hl1, hh2, hl2, hh3, hl3;
            split_bf16(h0, hh0, hl0); split_bf16(h1, hh1, hl1);
            split_bf16(h2, hh2, hl2); split_bf16(h3, hh3, hl3);
            __nv_bfloat16* op = o + (size_t)t * (2 * K2SPL);
            ((uint2*)op)[lane]            = make_uint2(pack2(hh0, hh1), pack2(hh2, hh3));
            ((uint2*)(op + K2SPL))[lane]  = make_uint2(pack2(hl0, hl1), pack2(hl2, hl3));
        }
    }

    if (!EMIT)
        *((float4*)(g_pend + (size_t)ch * 128) + lane) = make_float4(h0, h1, h2, h3);
}

// ---------------- chunk_mat (R15, proven) ----------
__global__ __launch_bounds__(256)
void chunk_mat()
{
    __shared__ __align__(16) float rec[2][4 * RECW2];
    const int ch = blockIdx.y;
    const int tid = threadIdx.x;
    const int col = blockIdx.x * 32 + (tid >> 3);
    const int q = tid & 7;

    const float* rbase = g_rec2 + (size_t)ch * LCH * RECW2;
    constexpr int BLKF = 4 * RECW2;

    float zc[8], yc[8];
#pragma unroll
    for (int i = 0; i < 8; i++) {
        int m = 8 * q + i;
        zc[i] = (m == col) ? 1.f : 0.f;
        yc[i] = (m + 64 == col) ? 1.f : 0.f;
    }

    for (int j = tid; j < BLKF; j += 256) rec[0][j] = rbase[j];
    __syncthreads();

    for (int blk = 0; blk < LCH / 4; blk++) {
        const int cur = blk & 1;
        const bool more = (blk + 1 < LCH / 4);
        float pf[7];
        if (more) {
            const float* rn = rbase + (size_t)(blk + 1) * BLKF;
#pragma unroll
            for (int j = 0; j < 7; j++) {
                int idx = tid + 256 * j;
                pf[j] = (idx < BLKF) ? rn[idx] : 0.f;
            }
        }

#pragma unroll
        for (int ts = 0; ts < 4; ts++) {
            const float* rc = &rec[cur][ts * RECW2];
            const float be1 = rc[384], be2 = rc[385], cc = rc[386];

            float Sm[8], Dm[8], K1z[8], K1y[8], K2z[8], K2y[8];
            *(float4*)&Sm[0]  = *(const float4*)(rc + 8 * q);
            *(float4*)&Sm[4]  = *(const float4*)(rc + 8 * q + 4);
            *(float4*)&Dm[0]  = *(const float4*)(rc + 64 + 8 * q);
            *(float4*)&Dm[4]  = *(const float4*)(rc + 64 + 8 * q + 4);
            *(float4*)&K1z[0] = *(const float4*)(rc + 128 + 8 * q);
            *(float4*)&K1z[4] = *(const float4*)(rc + 128 + 8 * q + 4);
            *(float4*)&K1y[0] = *(const float4*)(rc + 192 + 8 * q);
            *(float4*)&K1y[4] = *(const float4*)(rc + 192 + 8 * q + 4);
            *(float4*)&K2z[0] = *(const float4*)(rc + 256 + 8 * q);
            *(float4*)&K2z[4] = *(const float4*)(rc + 256 + 8 * q + 4);
            *(float4*)&K2y[0] = *(const float4*)(rc + 320 + 8 * q);
            *(float4*)&K2y[4] = *(const float4*)(rc + 320 + 8 * q + 4);

            float d1 = 0.f, d2 = 0.f;
#pragma unroll
            for (int i = 0; i < 8; i++) {
                float zn = fmaf(-Dm[i], yc[i], Sm[i] * zc[i]);
                float yn = Sm[i] * fmaf(0.1f, zc[i], yc[i]);
                d1 = fmaf(K1z[i], zn, fmaf(K1y[i], yn, d1));
                d2 = fmaf(K2z[i], zn, fmaf(K2y[i], yn, d2));
                zc[i] = zn; yc[i] = yn;
            }
#pragma unroll
            for (int off = 1; off < 8; off <<= 1) {
                d1 += __shfl_xor_sync(0xffffffffu, d1, off);
                d2 += __shfl_xor_sync(0xffffffffu, d2, off);
            }
            const float a1 = be1 * d1;
            const float a2 = be2 * fmaf(-cc, d1, d2);
#pragma unroll
            for (int i = 0; i < 8; i++) {
                zc[i] = fmaf(-a2, K2z[i], fmaf(-a1, K1z[i], zc[i]));
                yc[i] = fmaf(-a2, K2y[i], fmaf(-a1, K1y[i], yc[i]));
            }
        }

        if (more) {
            __syncthreads();
            float* dst = rec[cur ^ 1];
#pragma unroll
            for (int j = 0; j < 7; j++) {
                int idx = tid + 256 * j;
                if (idx < BLKF) dst[idx] = pf[j];
            }
            __syncthreads();
        }
    }

    float* ph = g_Phi + ((size_t)ch * 128 + col) * 128;
    *(float4*)(ph + 8 * q)          = make_float4(zc[0], zc[1], zc[2], zc[3]);
    *(float4*)(ph + 8 * q + 4)      = make_float4(zc[4], zc[5], zc[6], zc[7]);
    *(float4*)(ph + 64 + 8 * q)     = make_float4(yc[0], yc[1], yc[2], yc[3]);
    *(float4*)(ph + 64 + 8 * q + 4) = make_float4(yc[4], yc[5], yc[6], yc[7]);
}

// ---------------- combine (R15, proven) ----------
__global__ __launch_bounds__(128)
void combine()
{
    __shared__ float hs[128];
    const int b = blockIdx.x;
    const int tid = threadIdx.x;
    const int mi = 4 * (tid & 31) + (tid >> 5);

    hs[tid] = 0.f;
    __syncthreads();

    for (int c = 0; c < 16; c++) {
        const int ch = b * 16 + c;
        const float* __restrict__ Phi = g_Phi + (size_t)ch * 128 * 128;
        float y = 0.f;
#pragma unroll 16
        for (int col = 0; col < 128; col++)
            y = fmaf(Phi[(size_t)col * 128 + tid], hs[col], y);
        y += g_pend[(size_t)ch * 128 + mi];
        __syncthreads();
        hs[tid] = y;
        g_hend[(size_t)ch * 128 + mi] = y;
        __syncthreads();
    }
}

// ---------------- launch ----------------
extern "C" void kernel_launch(void* const* d_in, const int* in_sizes, int n_in,
                              void* d_out, int out_size)
{
    const float* u      = (const float*)d_in[0];
    const float* W_A    = (const float*)d_in[1];
    const float* b_A    = (const float*)d_in[2];
    const float* W_k    = (const float*)d_in[3];
    const float* b_k    = (const float*)d_in[4];
    const float* W_beta = (const float*)d_in[5];
    const float* b_beta = (const float*)d_in[6];
    const float* B_w    = (const float*)d_in[7];
    const float* B_b    = (const float*)d_in[8];
    const float* C      = (const float*)d_in[9];
    const float* D      = (const float*)d_in[10];
    float* out = (float*)d_out;

    static bool attr_done = false;
    if (!attr_done) {
        cudaFuncSetAttribute(mma_dedup<K1SPL, 32, false>,
                             cudaFuncAttributeMaxDynamicSharedMemorySize, 98304);
        cudaFuncSetAttribute(mma_dedup<K2SPL, 4, true>,
                             cudaFuncAttributeMaxDynamicSharedMemorySize, 98304);
        attr_done = true;
    }

    pack_b1<<<(NP * DMODEL + 255) / 256, 256>>>(W_A, W_k, W_beta, B_w);
    pack_b2<<<(DMODEL * 128 + 255) / 256, 256>>>(C);
    conv_u<<<(BT * (DMODEL / 4)) / 256, 256>>>(u);

    // GEMM1: P[16384 x 512] = dedup-split(u) x B1
    {
        __nv_bfloat16 *dA, *dB; float* dP;
        cudaGetSymbolAddress((void**)&dA, g_Uexp);
        cudaGetSymbolAddress((void**)&dB, g_B1);
        cudaGetSymbolAddress((void**)&dP, g_P);
        mma_dedup<K1SPL, 32, false><<<dim3(NP / 128, BT / 128), 256, 98304>>>(
            dA, dB, dP, NP, nullptr, nullptr);
    }

    derive_kernel<<<BT, 128>>>(b_A, b_k, b_beta, B_b);

    // chunked parallel scan
    scan_chunk<0><<<NCH / 4, 128>>>();
    chunk_mat<<<dim3(4, NCH), 256>>>();
    combine<<<BATCH, 128>>>();
    scan_chunk<1><<<NCH / 4, 128>>>();

    // GEMM2: out[16384 x 1024] = dedup-split(hs) x B2 + u * D
    {
        __nv_bfloat16 *dA, *dB;
        cudaGetSymbolAddress((void**)&dA, g_Hexp);
        cudaGetSymbolAddress((void**)&dB, g_B2);
        mma_dedup<K2SPL, 4, true><<<dim3(DMODEL / 128, BT / 128), 256, 98304>>>(
            dA, dB, out, DMODEL, u, D);
    }
}